// round 9
// baseline (speedup 1.0000x reference)
#include <cuda_runtime.h>
#include <cuda_bf16.h>
#include <math.h>
#include <stdint.h>

#define BH     32
#define NSEQ   4096
#define DDIM   64
#define MLAND  128
#define NBLK   128
#define SCALEF 0.3535533905932738f   /* 64^-0.25 */

/* ------------------ scratch: __device__ globals (no allocs) ------------------ */
__device__ __align__(16) float g_Wt[2048 * 64];
__device__ __align__(16) float g_QL[BH * MLAND * DDIM];
__device__ __align__(16) float g_ln[BH * MLAND];
__device__ __align__(16) float g_P [BH * MLAND * MLAND];
__device__ __align__(16) float g_P2[BH * MLAND * MLAND];
__device__ __align__(16) float g_VmA[BH * MLAND * MLAND];
__device__ __align__(16) float g_VmB[BH * MLAND * MLAND];
__device__ __align__(16) float g_cs[BH * MLAND];
__device__ __align__(16) float g_dg[BH * MLAND];
__device__ __align__(16) float g_kv [BH * MLAND * DDIM];
__device__ __align__(16) float g_kvp[16 * BH * MLAND * DDIM];
__device__ __align__(16) float g_Tm[BH * MLAND * DDIM];
__device__ __align__(16) float g_k1[(size_t)BH * NSEQ * MLAND]; /* 64 MB */
__device__ float    g_alpha;
__device__ unsigned g_maxrs;
__device__ unsigned g_maxc;
__device__ int      g_done;
__device__ int      g_cur;
__device__ int      g_bar_count;
__device__ int      g_bar_gen;

__device__ __forceinline__ uint32_t pack_bf2(__nv_bfloat16 a, __nv_bfloat16 b) {
    return (uint32_t)__bfloat16_as_ushort(a) | ((uint32_t)__bfloat16_as_ushort(b) << 16);
}
__device__ __forceinline__ void split2(float x, float y, uint32_t& hi, uint32_t& lo) {
    __nv_bfloat16 hx = __float2bfloat16(x), hy = __float2bfloat16(y);
    hi = pack_bf2(hx, hy);
    lo = pack_bf2(__float2bfloat16(x - __bfloat162float(hx)),
                  __float2bfloat16(y - __bfloat162float(hy)));
}
#define MMA_BF16(c, a0, a1, a2, a3, b0, b1)                                  \
    asm volatile("mma.sync.aligned.m16n8k16.row.col.f32.bf16.bf16.f32 "      \
        "{%0,%1,%2,%3}, {%4,%5,%6,%7}, {%8,%9}, {%0,%1,%2,%3};"              \
        : "+f"((c)[0]), "+f"((c)[1]), "+f"((c)[2]), "+f"((c)[3])             \
        : "r"(a0), "r"(a1), "r"(a2), "r"(a3), "r"(b0), "r"(b1))

/* split 128x128 fp32 (global, row stride 128) -> hi/lo u32 smem arrays (row stride 66 u32) */
__device__ __forceinline__ void split_tile_128(const float* __restrict__ g,
                                               uint32_t* hi, uint32_t* lo, int t) {
    for (int i = t; i < 8192; i += 256) {
        float2 v = ((const float2*)g)[i];
        uint32_t h, l;
        split2(v.x, v.y, h, l);
        int row = i >> 6, cp = i & 63;
        hi[row * 66 + cp] = h;
        lo[row * 66 + cp] = l;
    }
}

/* ------------------ 0. weight relayout (+ reset g_maxrs) ------------------ */
__global__ void wtrans_kernel(const float* __restrict__ W) {
    int idx = blockIdx.x * 256 + threadIdx.x;
    if (idx == 0) g_maxrs = 0u;
    int o = idx >> 11, i = (idx >> 5) & 63, k = idx & 31;
    g_Wt[(k * 64 + i) * 64 + o] = W[idx];
}

/* ------------------ 1. landmarks: GEMM + LayerNorm + exact GELU ------------------ */
__global__ void landmark_kernel(const float* __restrict__ Q,
                                const float* __restrict__ gamma,
                                const float* __restrict__ beta) {
    __shared__ float As[32][68];
    __shared__ float Ws[64][68];
    __shared__ float S[32][65];
    int bh = blockIdx.y, mb = blockIdx.x;
    int t = threadIdx.x;
    int tx = t & 63, ty = t >> 6;
    const float* qbase = Q + (size_t)bh * 262144 + (size_t)mb * 65536;
    float acc[8] = {0.f,0.f,0.f,0.f,0.f,0.f,0.f,0.f};
    for (int kc = 0; kc < 2048; kc += 64) {
        for (int idx = t; idx < 2048; idx += 256) {
            int r = idx >> 6, k = idx & 63;
            As[r][k] = qbase[r * 2048 + kc + k] * SCALEF;
        }
        for (int idx = t; idx < 4096; idx += 256) {
            int o = idx & 63, k = idx >> 6;
            Ws[o][k] = g_Wt[(kc + k) * 64 + o];
        }
        __syncthreads();
#pragma unroll
        for (int k4 = 0; k4 < 64; k4 += 4) {
            float4 w = *(const float4*)&Ws[tx][k4];
#pragma unroll
            for (int j = 0; j < 8; j++) {
                float4 a = *(const float4*)&As[ty * 8 + j][k4];
                acc[j] += a.x * w.x + a.y * w.y + a.z * w.z + a.w * w.w;
            }
        }
        __syncthreads();
    }
#pragma unroll
    for (int j = 0; j < 8; j++) S[ty * 8 + j][tx] = acc[j];
    __syncthreads();
    int warp = t >> 5, lane = t & 31;
    for (int rr = 0; rr < 4; rr++) {
        int row = warp * 4 + rr;
        float x0 = S[row][lane], x1 = S[row][lane + 32];
        float s = x0 + x1;
#pragma unroll
        for (int off = 16; off; off >>= 1) s += __shfl_xor_sync(0xffffffffu, s, off);
        float mu = s * (1.0f / 64.0f);
        float d0 = x0 - mu, d1 = x1 - mu;
        float v = d0 * d0 + d1 * d1;
#pragma unroll
        for (int off = 16; off; off >>= 1) v += __shfl_xor_sync(0xffffffffu, v, off);
        float rstd = rsqrtf(v * (1.0f / 64.0f) + 1e-5f);
        int mg = bh * 128 + mb * 32 + row;
#pragma unroll
        for (int cc = 0; cc < 2; cc++) {
            int c = lane + cc * 32;
            float x = cc ? x1 : x0;
            float y = (x - mu) * rstd * gamma[c] + beta[c];
            float g = 0.5f * y * (1.0f + erff(y * 0.70710678118654752f));
            g_QL[mg * 64 + c] = g;
        }
    }
}

/* ------------------ 2. P = k2 = exp(-0.5 sqdist(QL,QL)) ------------------ */
__global__ void k2_kernel() {
    __shared__ float QLt[64][132];
    __shared__ float lnorm[128];
    int bh = blockIdx.x, t = threadIdx.x;
    const float* ql = g_QL + bh * 8192;
    for (int idx = t; idx < 8192; idx += 256) {
        int m = idx >> 6, k = idx & 63;
        QLt[k][m] = ql[idx];
    }
    __syncthreads();
    if (t < 128) {
        float s = 0.f;
        for (int k = 0; k < 64; k++) { float v = QLt[k][t]; s += v * v; }
        lnorm[t] = s;
        g_ln[bh * 128 + t] = s;
    }
    __syncthreads();
    int tx = t & 15, ty = t >> 4;
    float acc[8][8];
#pragma unroll
    for (int i = 0; i < 8; i++)
#pragma unroll
        for (int j = 0; j < 8; j++) acc[i][j] = 0.f;
#pragma unroll 4
    for (int k = 0; k < 64; k++) {
        float4 a0 = *(const float4*)&QLt[k][ty * 8];
        float4 a1 = *(const float4*)&QLt[k][ty * 8 + 4];
        float4 b0 = *(const float4*)&QLt[k][tx * 8];
        float4 b1 = *(const float4*)&QLt[k][tx * 8 + 4];
        float a[8] = {a0.x,a0.y,a0.z,a0.w,a1.x,a1.y,a1.z,a1.w};
        float b[8] = {b0.x,b0.y,b0.z,b0.w,b1.x,b1.y,b1.z,b1.w};
#pragma unroll
        for (int i = 0; i < 8; i++)
#pragma unroll
            for (int j = 0; j < 8; j++) acc[i][j] += a[i] * b[j];
    }
    float* Ph = g_P + bh * 16384;
#pragma unroll
    for (int i = 0; i < 8; i++) {
        int m = ty * 8 + i;
        float o[8];
#pragma unroll
        for (int j = 0; j < 8; j++) {
            float d = lnorm[m] + lnorm[tx * 8 + j] - 2.0f * acc[i][j];
            d = fmaxf(d, 0.0f);
            o[j] = expf(-0.5f * d);
        }
        *(float4*)&Ph[m * 128 + tx * 8]     = make_float4(o[0], o[1], o[2], o[3]);
        *(float4*)&Ph[m * 128 + tx * 8 + 4] = make_float4(o[4], o[5], o[6], o[7]);
    }
}

/* ------------------ 3. k1 via mma.sync (HMMA) bf16-split, 3-pass ------------------ */
__global__ void __launch_bounds__(256) k1_hmma_kernel(const float* __restrict__ Q) {
    extern __shared__ unsigned char dsm[];
    float* Afp  = (float*)dsm;                       /* [128][66] */
    float* s_qn = (float*)(dsm + 33792);
    float* s_ln = s_qn + 128;
    __nv_bfloat16* Bh = (__nv_bfloat16*)(dsm + 34816);   /* [64][66] */
    __nv_bfloat16* Bl = Bh + 64 * 66;

    int t = threadIdx.x, lane = t & 31, w = t >> 5;
    int bh = blockIdx.y, n0 = blockIdx.x * 128;

    {
        int row = t >> 1, kh = (t & 1) * 32;
        const float* qrow = Q + (size_t)bh * 262144 + (size_t)(n0 + row) * 64 + kh;
        float part = 0.f;
#pragma unroll
        for (int i = 0; i < 8; i++) {
            float4 v = *(const float4*)&qrow[i * 4];
            float x0 = v.x * SCALEF, x1 = v.y * SCALEF;
            float x2 = v.z * SCALEF, x3 = v.w * SCALEF;
            part += x0 * x0 + x1 * x1 + x2 * x2 + x3 * x3;
            float* dst = &Afp[row * 66 + kh + i * 4];
            *(float2*)dst       = make_float2(x0, x1);
            *(float2*)(dst + 2) = make_float2(x2, x3);
        }
        part += __shfl_xor_sync(0xffffffffu, part, 1);
        if ((t & 1) == 0) s_qn[row] = part;
        if (t < 128) s_ln[t] = g_ln[bh * 128 + t];
    }

    float* k1h = g_k1 + (size_t)bh * 524288 + (size_t)n0 * 128;
    int r0 = w * 16;
    int row0 = r0 + (lane >> 2);
    int kq = (lane & 3) * 2;

    for (int half = 0; half < 2; half++) {
        __syncthreads();
        {
            int mrow = t >> 2, ks = (t & 3) * 16;
            const float* lrow = g_QL + bh * 8192 + (size_t)(half * 64 + mrow) * 64 + ks;
            uint32_t* bhp = (uint32_t*)(Bh + mrow * 66 + ks);
            uint32_t* blp = (uint32_t*)(Bl + mrow * 66 + ks);
#pragma unroll
            for (int i = 0; i < 4; i++) {
                float4 v = *(const float4*)&lrow[i * 4];
                uint32_t h0, l0, h1, l1;
                split2(v.x, v.y, h0, l0);
                split2(v.z, v.w, h1, l1);
                bhp[i * 2] = h0; bhp[i * 2 + 1] = h1;
                blp[i * 2] = l0; blp[i * 2 + 1] = l1;
            }
        }
        __syncthreads();

        float acc[8][4];
#pragma unroll
        for (int i = 0; i < 8; i++)
#pragma unroll
            for (int j = 0; j < 4; j++) acc[i][j] = 0.f;

#pragma unroll
        for (int ks = 0; ks < 4; ks++) {
            int k0 = ks * 16 + kq;
            float2 v00 = *(const float2*)&Afp[row0 * 66 + k0];
            float2 v10 = *(const float2*)&Afp[(row0 + 8) * 66 + k0];
            float2 v01 = *(const float2*)&Afp[row0 * 66 + k0 + 8];
            float2 v11 = *(const float2*)&Afp[(row0 + 8) * 66 + k0 + 8];
            uint32_t ah0, al0, ah1, al1, ah2, al2, ah3, al3;
            split2(v00.x, v00.y, ah0, al0);
            split2(v10.x, v10.y, ah1, al1);
            split2(v01.x, v01.y, ah2, al2);
            split2(v11.x, v11.y, ah3, al3);
#pragma unroll
            for (int tile = 0; tile < 8; tile++) {
                int n = tile * 8 + (lane >> 2);
                const uint32_t* bhp = (const uint32_t*)(Bh + n * 66 + k0);
                const uint32_t* blp = (const uint32_t*)(Bl + n * 66 + k0);
                uint32_t bh0 = bhp[0], bh1 = bhp[4];
                uint32_t bl0 = blp[0], bl1 = blp[4];
                MMA_BF16(acc[tile], ah0, ah1, ah2, ah3, bh0, bh1);
                MMA_BF16(acc[tile], ah0, ah1, ah2, ah3, bl0, bl1);
                MMA_BF16(acc[tile], al0, al1, al2, al3, bh0, bh1);
            }
        }

        float qn0 = s_qn[row0], qn1 = s_qn[row0 + 8];
#pragma unroll
        for (int tile = 0; tile < 8; tile++) {
            int col = half * 64 + tile * 8 + kq;
            float l0 = s_ln[col], l1 = s_ln[col + 1];
            float d00 = fmaxf(qn0 + l0 - 2.0f * acc[tile][0], 0.f);
            float d01 = fmaxf(qn0 + l1 - 2.0f * acc[tile][1], 0.f);
            float d10 = fmaxf(qn1 + l0 - 2.0f * acc[tile][2], 0.f);
            float d11 = fmaxf(qn1 + l1 - 2.0f * acc[tile][3], 0.f);
            *(float2*)&k1h[(size_t)row0 * 128 + col] =
                make_float2(__expf(-0.5f * d00), __expf(-0.5f * d01));
            *(float2*)&k1h[(size_t)(row0 + 8) * 128 + col] =
                make_float2(__expf(-0.5f * d10), __expf(-0.5f * d11));
        }
    }
}

/* ------------------ 4a. global max rowsum(P) ------------------ */
__global__ void rowmax_kernel() {
    __shared__ float red[128];
    int bh = blockIdx.x, t = threadIdx.x;
    const float* Ph = g_P + bh * 16384;
    float s = 0.f;
    for (int k = 0; k < 128; k++) s += Ph[t * 128 + k];
    red[t] = s;
    __syncthreads();
    for (int st = 64; st; st >>= 1) {
        if (t < st) red[t] = fmaxf(red[t], red[t + st]);
        __syncthreads();
    }
    if (t == 0) atomicMax(&g_maxrs, __float_as_uint(red[0]));
}

/* ------------------ batched mm: sel0 P2=P@P (nB=128), sel1 Tm=Vm@kv (nB=64) ------------------ */
__global__ void mm_bk(int sel) {
    const float *A, *B; float* C; int nB;
    if (sel == 0) { A = g_P;  B = g_P;  C = g_P2; nB = 128; }
    else {
        A = (*(volatile int*)&g_cur) ? g_VmB : g_VmA;
        B = g_kv; C = g_Tm; nB = 64;
    }
    int bh = blockIdx.y;
    int ntx = nB >> 6;
    int tm = (blockIdx.x / ntx) * 64, tn = (blockIdx.x % ntx) * 64;
    const float* Ah = A + bh * 16384;
    const float* Bh = B + bh * 128 * nB;
    float* Ch = C + bh * 128 * nB;
    __shared__ float At[16][68], Bt[16][68];
    int t = threadIdx.x, tx = t & 15, ty = t >> 4;
    float acc[4][4];
#pragma unroll
    for (int i = 0; i < 4; i++)
#pragma unroll
        for (int j = 0; j < 4; j++) acc[i][j] = 0.f;
    for (int kc = 0; kc < 128; kc += 16) {
        {
            int r = t >> 2, kq = (t & 3) << 2;
            float4 v = *(const float4*)&Ah[(tm + r) * 128 + kc + kq];
            At[kq + 0][r] = v.x; At[kq + 1][r] = v.y;
            At[kq + 2][r] = v.z; At[kq + 3][r] = v.w;
        }
        {
            int k = t >> 4, cq = (t & 15) << 2;
            *(float4*)&Bt[k][cq] = *(const float4*)&Bh[(kc + k) * nB + tn + cq];
        }
        __syncthreads();
#pragma unroll
        for (int k = 0; k < 16; k++) {
            float4 av = *(const float4*)&At[k][ty * 4];
            float4 bv = *(const float4*)&Bt[k][tx * 4];
            float a[4] = {av.x, av.y, av.z, av.w};
            float b[4] = {bv.x, bv.y, bv.z, bv.w};
#pragma unroll
            for (int i = 0; i < 4; i++)
#pragma unroll
                for (int j = 0; j < 4; j++) acc[i][j] += a[i] * b[j];
        }
        __syncthreads();
    }
#pragma unroll
    for (int i = 0; i < 4; i++) {
        int row = tm + ty * 4 + i;
        *(float4*)&Ch[row * nB + tn + tx * 4] =
            make_float4(acc[i][0], acc[i][1], acc[i][2], acc[i][3]);
    }
}

/* ------------------ 4b. column sums + diag of P2 ------------------ */
__global__ void colsum_kernel() {
    int bh = blockIdx.x, j = threadIdx.x;
    const float* P2h = g_P2 + bh * 16384;
    float s = 0.f;
    for (int i = 0; i < 128; i++) s += P2h[i * 128 + j];
    g_cs[bh * 128 + j] = s;
    g_dg[bh * 128 + j] = P2h[j * 128 + j];
}

/* ------------------ 4c. alpha init + 10 halvings (one block) ------------------ */
__global__ void alpha_kernel() {
    __shared__ float red[256];
    __shared__ float sh_alpha;
    int t = threadIdx.x;
    if (t == 0) {
        float mr = __uint_as_float(g_maxrs);
        sh_alpha = 2.0f / (mr * mr);
    }
    __syncthreads();
    for (int it = 0; it < 10; it++) {
        float a = sh_alpha;
        float mx = 0.f;
        for (int idx = t; idx < 4096; idx += 256) {
            float cs = g_cs[idx], dg = g_dg[idx];
            float v = a * (cs - dg) + fabsf(1.0f - a * dg);
            mx = fmaxf(mx, v);
        }
        red[t] = mx;
        __syncthreads();
        for (int st = 128; st; st >>= 1) {
            if (t < st) red[t] = fmaxf(red[t], red[t + st]);
            __syncthreads();
        }
        if (t == 0 && red[0] > 1.01f) sh_alpha = a * 0.5f;
        __syncthreads();
    }
    if (t == 0) { g_alpha = sh_alpha; g_done = 0; g_maxc = 0u; g_cur = 0; }
}

/* ------------------ 4d. VmA = alpha * P ------------------ */
__global__ void vminit_kernel() {
    int i = blockIdx.x * 256 + threadIdx.x;
    float a = g_alpha;
    float4 p = ((const float4*)g_P)[i];
    ((float4*)g_VmA)[i] = make_float4(a * p.x, a * p.y, a * p.z, a * p.w);
}

/* ------------------ 5. persistent Newton via HMMA (P, Vm symmetric) ------------------ */
__device__ __forceinline__ void gbar() {
    __syncthreads();
    if (threadIdx.x == 0) {
        __threadfence();
        int gen = *(volatile int*)&g_bar_gen;
        if (atomicAdd(&g_bar_count, 1) == NBLK - 1) {
            g_bar_count = 0;
            __threadfence();
            *(volatile int*)&g_bar_gen = gen + 1;
        } else {
            while (*(volatile int*)&g_bar_gen == gen) __nanosleep(64);
        }
    }
    __syncthreads();
}

__global__ void __launch_bounds__(256, 1) newton_persistent() {
    extern __shared__ unsigned char dsm[];
    uint32_t* Phu = (uint32_t*)dsm;          /* [128][66] u32 */
    uint32_t* Plu = Phu + 8448;
    uint32_t* Vhu = Phu + 16896;
    uint32_t* Vlu = Phu + 25344;
    uint32_t* Thu = Phu + 33792;             /* [32][66] */
    uint32_t* Tlu = Phu + 35904;             /* total 38016 u32 = 152064 B */
    __shared__ float red[256];

    int t = threadIdx.x, lane = t & 31, w = t >> 5;
    int wr = w >> 2, wc = w & 3;
    int g = lane >> 2, tq = lane & 3;
    int bh = blockIdx.x >> 2;
    int r0 = (blockIdx.x & 3) * 32;
    const float* Pg = g_P + bh * 16384;

    split_tile_128(Pg, Phu, Plu, t);

    for (int it = 0; it < 20; it++) {
        if (!(*(volatile int*)&g_done)) {
            int cur = *(volatile int*)&g_cur;
            const float* Vmg = (cur ? g_VmB : g_VmA) + bh * 16384;
            float*       Cg  = (cur ? g_VmA : g_VmB) + bh * 16384;
            __syncthreads();
            split_tile_128(Vmg, Vhu, Vlu, t);
            __syncthreads();

            float acc[4][4];
#pragma unroll
            for (int i = 0; i < 4; i++)
#pragma unroll
                for (int j = 0; j < 4; j++) acc[i][j] = 0.f;
            int rA = r0 + wr * 16 + g;
#pragma unroll
            for (int ks = 0; ks < 8; ks++) {
                int ko = ks * 8 + tq;
                uint32_t ah0 = Vhu[rA * 66 + ko],        ah1 = Vhu[(rA + 8) * 66 + ko];
                uint32_t ah2 = Vhu[rA * 66 + ko + 4],    ah3 = Vhu[(rA + 8) * 66 + ko + 4];
                uint32_t al0 = Vlu[rA * 66 + ko],        al1 = Vlu[(rA + 8) * 66 + ko];
                uint32_t al2 = Vlu[rA * 66 + ko + 4],    al3 = Vlu[(rA + 8) * 66 + ko + 4];
#pragma unroll
                for (int tile = 0; tile < 4; tile++) {
                    int n = wc * 32 + tile * 8 + g;
                    uint32_t bh0 = Phu[n * 66 + ko], bh1 = Phu[n * 66 + ko + 4];
                    uint32_t bl0 = Plu[n * 66 + ko], bl1 = Plu[n * 66 + ko + 4];
                    MMA_BF16(acc[tile], ah0, ah1, ah2, ah3, bh0, bh1);
                    MMA_BF16(acc[tile], ah0, ah1, ah2, ah3, bl0, bl1);
                    MMA_BF16(acc[tile], al0, al1, al2, al3, bh0, bh1);
                }
            }
            int trl = wr * 16 + g;
#pragma unroll
            for (int tile = 0; tile < 4; tile++) {
                int c2 = wc * 16 + tile * 4 + tq;
                uint32_t h, l;
                split2(acc[tile][0], acc[tile][1], h, l);
                Thu[trl * 66 + c2] = h; Tlu[trl * 66 + c2] = l;
                split2(acc[tile][2], acc[tile][3], h, l);
                Thu[(trl + 8) * 66 + c2] = h; Tlu[(trl + 8) * 66 + c2] = l;
            }
            __syncthreads();

#pragma unroll
            for (int i = 0; i < 4; i++)
#pragma unroll
                for (int j = 0; j < 4; j++) acc[i][j] = 0.f;
#pragma unroll
            for (int ks = 0; ks < 8; ks++) {
                int ko = ks * 8 + tq;
                uint32_t ah0 = Thu[trl * 66 + ko],       ah1 = Thu[(trl + 8) * 66 + ko];
                uint32_t ah2 = Thu[trl * 66 + ko + 4],   ah3 = Thu[(trl + 8) * 66 + ko + 4];
                uint32_t al0 = Tlu[trl * 66 + ko],       al1 = Tlu[(trl + 8) * 66 + ko];
                uint32_t al2 = Tlu[trl * 66 + ko + 4],   al3 = Tlu[(trl + 8) * 66 + ko + 4];
#pragma unroll
                for (int tile = 0; tile < 4; tile++) {
                    int n = wc * 32 + tile * 8 + g;
                    uint32_t bh0 = Vhu[n * 66 + ko], bh1 = Vhu[n * 66 + ko + 4];
                    uint32_t bl0 = Vlu[n * 66 + ko], bl1 = Vlu[n * 66 + ko + 4];
                    MMA_BF16(acc[tile], ah0, ah1, ah2, ah3, bh0, bh1);
                    MMA_BF16(acc[tile], ah0, ah1, ah2, ah3, bl0, bl1);
                    MMA_BF16(acc[tile], al0, al1, al2, al3, bh0, bh1);
                }
            }
            float mx = 0.f;
            int rowg = r0 + wr * 16 + g;
#pragma unroll
            for (int tile = 0; tile < 4; tile++) {
                int c = wc * 32 + tile * 8 + 2 * tq;
                float2 vm0 = *(const float2*)&Vmg[rowg * 128 + c];
                float2 vm1 = *(const float2*)&Vmg[(rowg + 8) * 128 + c];
                float o0 = 2.0f * vm0.x - acc[tile][0];
                float o1 = 2.0f * vm0.y - acc[tile][1];
                float o2 = 2.0f * vm1.x - acc[tile][2];
                float o3 = 2.0f * vm1.y - acc[tile][3];
                mx = fmaxf(mx, fmaxf(fmaxf(fabsf(o0), fabsf(o1)),
                                     fmaxf(fabsf(o2), fabsf(o3))));
                *(float2*)&Cg[rowg * 128 + c]       = make_float2(o0, o1);
                *(float2*)&Cg[(rowg + 8) * 128 + c] = make_float2(o2, o3);
            }
            red[t] = mx;
            __syncthreads();
            for (int st = 128; st; st >>= 1) {
                if (t < st) red[t] = fmaxf(red[t], red[t + st]);
                __syncthreads();
            }
            if (t == 0) atomicMax(&g_maxc, __float_as_uint(red[0]));
        }
        gbar();
        if (blockIdx.x == 0 && t == 0) {
            if (!g_done) {
                float m = __uint_as_float(g_maxc);
                if (m > 10000.0f) g_done = 1;
                else              g_cur ^= 1;
                g_maxc = 0u;
            }
        }
        gbar();
    }
}

/* ------------------ 6. kv via HMMA: kv = k1^T @ V, split-K=8 over n ------------------
 * A = k1^T [128m][n], B = V^T [64d][n]; both transposed+split during staging.
 * bf16x2 packs two consecutive n. Smem stride 33 u32 (conflict-free).
 */
__global__ void __launch_bounds__(256) kv_hmma_kernel(const float* __restrict__ V) {
    extern __shared__ unsigned char dsm[];
    uint32_t* Ahu = (uint32_t*)dsm;          /* [128][33] u32 */
    uint32_t* Alu = Ahu + 4224;
    uint32_t* Bhu = Ahu + 8448;              /* [64][33] */
    uint32_t* Blu = Ahu + 10560;             /* total 12672 u32 = 50688 B */

    int t = threadIdx.x, lane = t & 31, w = t >> 5;
    int g = lane >> 2, tq = lane & 3;
    int c = blockIdx.x, bh = blockIdx.y;
    const float* k1h = g_k1 + (size_t)bh * 524288;
    const float* Vh  = V + (size_t)bh * 262144;

    float acc[8][4];
#pragma unroll
    for (int i = 0; i < 8; i++)
#pragma unroll
        for (int j = 0; j < 4; j++) acc[i][j] = 0.f;

    for (int sub = 0; sub < 8; sub++) {
        int nb = c * 512 + sub * 64;
        __syncthreads();
        /* stage A: k1^T tile [128m][32np], np packs n pair */
        for (int i = t; i < 4096; i += 256) {
            int np = i >> 7, m = i & 127;
            size_t base = (size_t)(nb + 2 * np) * 128 + m;
            float x = k1h[base], y = k1h[base + 128];
            uint32_t h, l;
            split2(x, y, h, l);
            Ahu[m * 33 + np] = h;
            Alu[m * 33 + np] = l;
        }
        /* stage B: V^T tile [64d][32np] */
        for (int i = t; i < 2048; i += 256) {
            int np = i >> 6, d = i & 63;
            size_t base = (size_t)(nb + 2 * np) * 64 + d;
            float x = Vh[base], y = Vh[base + 64];
            uint32_t h, l;
            split2(x, y, h, l);
            Bhu[d * 33 + np] = h;
            Blu[d * 33 + np] = l;
        }
        __syncthreads();

        int rA = w * 16 + g;
#pragma unroll
        for (int ks = 0; ks < 4; ks++) {
            int ko = ks * 8 + tq;
            uint32_t ah0 = Ahu[rA * 33 + ko],       ah1 = Ahu[(rA + 8) * 33 + ko];
            uint32_t ah2 = Ahu[rA * 33 + ko + 4],   ah3 = Ahu[(rA + 8) * 33 + ko + 4];
            uint32_t al0 = Alu[rA * 33 + ko],       al1 = Alu[(rA + 8) * 33 + ko];
            uint32_t al2 = Alu[rA * 33 + ko + 4],   al3 = Alu[(rA + 8) * 33 + ko + 4];
#pragma unroll
            for (int tile = 0; tile < 8; tile++) {
                int d = tile * 8 + g;
                uint32_t bh0 = Bhu[d * 33 + ko], bh1 = Bhu[d * 33 + ko + 4];
                uint32_t bl0 = Blu[d * 33 + ko], bl1 = Blu[d * 33 + ko + 4];
                MMA_BF16(acc[tile], ah0, ah1, ah2, ah3, bh0, bh1);
                MMA_BF16(acc[tile], ah0, ah1, ah2, ah3, bl0, bl1);
                MMA_BF16(acc[tile], al0, al1, al2, al3, bh0, bh1);
            }
        }
    }

    /* write partials: kvp[m][d] */
    float* kvp = g_kvp + (size_t)(c * 32 + bh) * 8192;
    int rA = w * 16 + g;
#pragma unroll
    for (int tile = 0; tile < 8; tile++) {
        int d = tile * 8 + 2 * tq;
        *(float2*)&kvp[rA * 64 + d]       = make_float2(acc[tile][0], acc[tile][1]);
        *(float2*)&kvp[(rA + 8) * 64 + d] = make_float2(acc[tile][2], acc[tile][3]);
    }
}

__global__ void kvreduce_kernel() {
    int o = blockIdx.x * 256 + threadIdx.x;
    float s = 0.f;
    for (int c = 0; c < 8; c++) s += g_kvp[(size_t)c * 262144 + o];
    g_kv[o] = s;
}

/* ------------------ 7. final via HMMA: X = k1 @ Tm + depthwise conv(V) ------------------ */
__global__ void __launch_bounds__(256) final_hmma_kernel(const float* __restrict__ V,
                                                         const float* __restrict__ cw,
                                                         float* __restrict__ out) {
    extern __shared__ unsigned char dsm[];
    uint32_t* K1hu  = (uint32_t*)dsm;        /* [128][66] u32 */
    uint32_t* K1lu  = K1hu + 8448;
    uint32_t* TmThu = K1hu + 16896;          /* [64][66] u32 : TmT[d][m] */
    uint32_t* TmTlu = K1hu + 21120;          /* total 25344 u32 = 101376 B */

    int t = threadIdx.x, lane = t & 31, w = t >> 5;
    int g = lane >> 2, tq = lane & 3;
    int bh = blockIdx.y, n0 = blockIdx.x * 128;
    const float* k1g = g_k1 + (size_t)bh * 524288 + (size_t)n0 * 128;
    const float* Tmg = g_Tm + bh * 8192;

    split_tile_128(k1g, K1hu, K1lu, t);
    for (int i = t; i < 4096; i += 256) {
        int d = i >> 6, mp = i & 63;
        float x = Tmg[(2 * mp) * 64 + d];
        float y = Tmg[(2 * mp + 1) * 64 + d];
        uint32_t h, l;
        split2(x, y, h, l);
        TmThu[d * 66 + mp] = h;
        TmTlu[d * 66 + mp] = l;
    }
    __syncthreads();

    float acc[8][4];
#pragma unroll
    for (int i = 0; i < 8; i++)
#pragma unroll
        for (int j = 0; j < 4; j++) acc[i][j] = 0.f;
    int rA = w * 16 + g;
#pragma unroll
    for (int ks = 0; ks < 8; ks++) {
        int ko = ks * 8 + tq;
        uint32_t ah0 = K1hu[rA * 66 + ko],       ah1 = K1hu[(rA + 8) * 66 + ko];
        uint32_t ah2 = K1hu[rA * 66 + ko + 4],   ah3 = K1hu[(rA + 8) * 66 + ko + 4];
        uint32_t al0 = K1lu[rA * 66 + ko],       al1 = K1lu[(rA + 8) * 66 + ko];
        uint32_t al2 = K1lu[rA * 66 + ko + 4],   al3 = K1lu[(rA + 8) * 66 + ko + 4];
#pragma unroll
        for (int tile = 0; tile < 8; tile++) {
            int n = tile * 8 + g;
            uint32_t bh0 = TmThu[n * 66 + ko], bh1 = TmThu[n * 66 + ko + 4];
            uint32_t bl0 = TmTlu[n * 66 + ko], bl1 = TmTlu[n * 66 + ko + 4];
            MMA_BF16(acc[tile], ah0, ah1, ah2, ah3, bh0, bh1);
            MMA_BF16(acc[tile], ah0, ah1, ah2, ah3, bl0, bl1);
            MMA_BF16(acc[tile], al0, al1, al2, al3, bh0, bh1);
        }
    }

    int h = bh & 15;
    float w0 = cw[h * 3], w1 = cw[h * 3 + 1], w2 = cw[h * 3 + 2];
    const float* Vh = V + (size_t)bh * 262144;
    float* oh = out + (size_t)bh * 262144;
#pragma unroll
    for (int tile = 0; tile < 8; tile++) {
        int d = tile * 8 + 2 * tq;
#pragma unroll
        for (int rr = 0; rr < 2; rr++) {
            int n = n0 + w * 16 + g + rr * 8;
            float a0 = acc[tile][rr * 2], a1 = acc[tile][rr * 2 + 1];
            float2 vc = *(const float2*)&Vh[(size_t)n * 64 + d];
            float2 vp = (n > 0)    ? *(const float2*)&Vh[(size_t)(n - 1) * 64 + d] : make_float2(0.f, 0.f);
            float2 vn = (n < 4095) ? *(const float2*)&Vh[(size_t)(n + 1) * 64 + d] : make_float2(0.f, 0.f);
            float2 o;
            o.x = a0 + w0 * vp.x + w1 * vc.x + w2 * vn.x;
            o.y = a1 + w0 * vp.y + w1 * vc.y + w2 * vn.y;
            *(float2*)&oh[(size_t)n * 64 + d] = o;
        }
    }
}

/* ------------------ launch ------------------ */
extern "C" void kernel_launch(void* const* d_in, const int* in_sizes, int n_in,
                              void* d_out, int out_size) {
    (void)in_sizes; (void)n_in; (void)out_size;
    const float* Q     = (const float*)d_in[0];
    const float* V     = (const float*)d_in[1];
    const float* Wland = (const float*)d_in[2];
    const float* gamma = (const float*)d_in[3];
    const float* beta  = (const float*)d_in[4];
    const float* convw = (const float*)d_in[5];
    float* out = (float*)d_out;

    cudaFuncSetAttribute(k1_hmma_kernel,
                         cudaFuncAttributeMaxDynamicSharedMemorySize, 52224);
    cudaFuncSetAttribute(newton_persistent,
                         cudaFuncAttributeMaxDynamicSharedMemorySize, 152064);
    cudaFuncSetAttribute(final_hmma_kernel,
                         cudaFuncAttributeMaxDynamicSharedMemorySize, 101376);
    cudaFuncSetAttribute(kv_hmma_kernel,
                         cudaFuncAttributeMaxDynamicSharedMemorySize, 50688);

    wtrans_kernel<<<512, 256>>>(Wland);
    landmark_kernel<<<dim3(4, BH), 256>>>(Q, gamma, beta);
    k2_kernel<<<BH, 256>>>();
    k1_hmma_kernel<<<dim3(32, BH), 256, 51712>>>(Q);
    rowmax_kernel<<<BH, 128>>>();
    mm_bk<<<dim3(4, BH), 256>>>(0);               /* P2 = P @ P */
    colsum_kernel<<<BH, 128>>>();
    alpha_kernel<<<1, 256>>>();
    vminit_kernel<<<512, 256>>>();
    newton_persistent<<<NBLK, 256, 152064>>>();
    kv_hmma_kernel<<<dim3(8, BH), 256, 50688>>>(V);
    kvreduce_kernel<<<1024, 256>>>();
    mm_bk<<<dim3(2, BH), 256>>>(1);               /* Tm = Vm @ kv */
    final_hmma_kernel<<<dim3(32, BH), 256, 101376>>>(V, convw, out);
}

// round 11
// speedup vs baseline: 1.0590x; 1.0590x over previous
#include <cuda_runtime.h>
#include <cuda_bf16.h>
#include <math.h>
#include <stdint.h>

#define BH     32
#define NSEQ   4096
#define DDIM   64
#define MLAND  128
#define NBLK   128
#define SCALEF 0.3535533905932738f   /* 64^-0.25 */

/* ------------------ scratch: __device__ globals (no allocs) ------------------ */
__device__ __align__(16) float g_Wt[2048 * 64];
__device__ __align__(16) float g_QL[BH * MLAND * DDIM];
__device__ __align__(16) float g_ln[BH * MLAND];
__device__ __align__(16) float g_P [BH * MLAND * MLAND];
__device__ __align__(16) float g_VmA[BH * MLAND * MLAND];
__device__ __align__(16) float g_VmB[BH * MLAND * MLAND];
__device__ __align__(16) float g_cs[BH * MLAND];
__device__ __align__(16) float g_dg[BH * MLAND];
__device__ __align__(16) float g_kv [BH * MLAND * DDIM];
__device__ __align__(16) float g_kvp[16 * BH * MLAND * DDIM];
__device__ __align__(16) float g_Tm[BH * MLAND * DDIM];
__device__ __align__(16) float g_k1[(size_t)BH * NSEQ * MLAND]; /* 64 MB */
__device__ float    g_alpha;
__device__ unsigned g_maxrs;
__device__ unsigned g_maxc;
__device__ int      g_done;
__device__ int      g_cur;
__device__ int      g_bar_count;
__device__ int      g_bar_gen;

__device__ __forceinline__ uint32_t pack_bf2(__nv_bfloat16 a, __nv_bfloat16 b) {
    return (uint32_t)__bfloat16_as_ushort(a) | ((uint32_t)__bfloat16_as_ushort(b) << 16);
}
__device__ __forceinline__ void split2(float x, float y, uint32_t& hi, uint32_t& lo) {
    __nv_bfloat16 hx = __float2bfloat16(x), hy = __float2bfloat16(y);
    hi = pack_bf2(hx, hy);
    lo = pack_bf2(__float2bfloat16(x - __bfloat162float(hx)),
                  __float2bfloat16(y - __bfloat162float(hy)));
}
#define MMA_BF16(c, a0, a1, a2, a3, b0, b1)                                  \
    asm volatile("mma.sync.aligned.m16n8k16.row.col.f32.bf16.bf16.f32 "      \
        "{%0,%1,%2,%3}, {%4,%5,%6,%7}, {%8,%9}, {%0,%1,%2,%3};"              \
        : "+f"((c)[0]), "+f"((c)[1]), "+f"((c)[2]), "+f"((c)[3])             \
        : "r"(a0), "r"(a1), "r"(a2), "r"(a3), "r"(b0), "r"(b1))

/* split 128x128 fp32 (global, row stride 128) -> hi/lo u32 smem (row stride 66) */
__device__ __forceinline__ void split_tile_128(const float* __restrict__ g,
                                               uint32_t* hi, uint32_t* lo, int t) {
    for (int i = t; i < 8192; i += 256) {
        float2 v = ((const float2*)g)[i];
        uint32_t h, l;
        split2(v.x, v.y, h, l);
        int row = i >> 6, cp = i & 63;
        hi[row * 66 + cp] = h;
        lo[row * 66 + cp] = l;
    }
}

/* ------------------ 0. weight relayout (+ reset g_maxrs) ------------------ */
__global__ void wtrans_kernel(const float* __restrict__ W) {
    int idx = blockIdx.x * 256 + threadIdx.x;
    if (idx == 0) g_maxrs = 0u;
    int o = idx >> 11, i = (idx >> 5) & 63, k = idx & 31;
    g_Wt[(k * 64 + i) * 64 + o] = W[idx];
}

/* ------------------ 1. landmarks: GEMM + LayerNorm + exact GELU ------------------ */
__global__ void landmark_kernel(const float* __restrict__ Q,
                                const float* __restrict__ gamma,
                                const float* __restrict__ beta) {
    __shared__ float As[32][68];
    __shared__ float Ws[64][68];
    __shared__ float S[32][65];
    int bh = blockIdx.y, mb = blockIdx.x;
    int t = threadIdx.x;
    int tx = t & 63, ty = t >> 6;
    const float* qbase = Q + (size_t)bh * 262144 + (size_t)mb * 65536;
    float acc[8] = {0.f,0.f,0.f,0.f,0.f,0.f,0.f,0.f};
    for (int kc = 0; kc < 2048; kc += 64) {
        for (int idx = t; idx < 2048; idx += 256) {
            int r = idx >> 6, k = idx & 63;
            As[r][k] = qbase[r * 2048 + kc + k] * SCALEF;
        }
        for (int idx = t; idx < 4096; idx += 256) {
            int o = idx & 63, k = idx >> 6;
            Ws[o][k] = g_Wt[(kc + k) * 64 + o];
        }
        __syncthreads();
#pragma unroll
        for (int k4 = 0; k4 < 64; k4 += 4) {
            float4 w = *(const float4*)&Ws[tx][k4];
#pragma unroll
            for (int j = 0; j < 8; j++) {
                float4 a = *(const float4*)&As[ty * 8 + j][k4];
                acc[j] += a.x * w.x + a.y * w.y + a.z * w.z + a.w * w.w;
            }
        }
        __syncthreads();
    }
#pragma unroll
    for (int j = 0; j < 8; j++) S[ty * 8 + j][tx] = acc[j];
    __syncthreads();
    int warp = t >> 5, lane = t & 31;
    for (int rr = 0; rr < 4; rr++) {
        int row = warp * 4 + rr;
        float x0 = S[row][lane], x1 = S[row][lane + 32];
        float s = x0 + x1;
#pragma unroll
        for (int off = 16; off; off >>= 1) s += __shfl_xor_sync(0xffffffffu, s, off);
        float mu = s * (1.0f / 64.0f);
        float d0 = x0 - mu, d1 = x1 - mu;
        float v = d0 * d0 + d1 * d1;
#pragma unroll
        for (int off = 16; off; off >>= 1) v += __shfl_xor_sync(0xffffffffu, v, off);
        float rstd = rsqrtf(v * (1.0f / 64.0f) + 1e-5f);
        int mg = bh * 128 + mb * 32 + row;
#pragma unroll
        for (int cc = 0; cc < 2; cc++) {
            int c = lane + cc * 32;
            float x = cc ? x1 : x0;
            float y = (x - mu) * rstd * gamma[c] + beta[c];
            float g = 0.5f * y * (1.0f + erff(y * 0.70710678118654752f));
            g_QL[mg * 64 + c] = g;
        }
    }
}

/* ------------------ 2. P = k2 = exp(-0.5 sqdist(QL,QL)) ------------------ */
__global__ void k2_kernel() {
    __shared__ float QLt[64][132];
    __shared__ float lnorm[128];
    int bh = blockIdx.x, t = threadIdx.x;
    const float* ql = g_QL + bh * 8192;
    for (int idx = t; idx < 8192; idx += 256) {
        int m = idx >> 6, k = idx & 63;
        QLt[k][m] = ql[idx];
    }
    __syncthreads();
    if (t < 128) {
        float s = 0.f;
        for (int k = 0; k < 64; k++) { float v = QLt[k][t]; s += v * v; }
        lnorm[t] = s;
        g_ln[bh * 128 + t] = s;
    }
    __syncthreads();
    int tx = t & 15, ty = t >> 4;
    float acc[8][8];
#pragma unroll
    for (int i = 0; i < 8; i++)
#pragma unroll
        for (int j = 0; j < 8; j++) acc[i][j] = 0.f;
#pragma unroll 4
    for (int k = 0; k < 64; k++) {
        float4 a0 = *(const float4*)&QLt[k][ty * 8];
        float4 a1 = *(const float4*)&QLt[k][ty * 8 + 4];
        float4 b0 = *(const float4*)&QLt[k][tx * 8];
        float4 b1 = *(const float4*)&QLt[k][tx * 8 + 4];
        float a[8] = {a0.x,a0.y,a0.z,a0.w,a1.x,a1.y,a1.z,a1.w};
        float b[8] = {b0.x,b0.y,b0.z,b0.w,b1.x,b1.y,b1.z,b1.w};
#pragma unroll
        for (int i = 0; i < 8; i++)
#pragma unroll
            for (int j = 0; j < 8; j++) acc[i][j] += a[i] * b[j];
    }
    float* Ph = g_P + bh * 16384;
#pragma unroll
    for (int i = 0; i < 8; i++) {
        int m = ty * 8 + i;
        float o[8];
#pragma unroll
        for (int j = 0; j < 8; j++) {
            float d = lnorm[m] + lnorm[tx * 8 + j] - 2.0f * acc[i][j];
            d = fmaxf(d, 0.0f);
            o[j] = expf(-0.5f * d);
        }
        *(float4*)&Ph[m * 128 + tx * 8]     = make_float4(o[0], o[1], o[2], o[3]);
        *(float4*)&Ph[m * 128 + tx * 8 + 4] = make_float4(o[4], o[5], o[6], o[7]);
    }
}

/* ------------------ 3. k1 via mma.sync (HMMA) bf16-split, 3-pass ------------------ */
__global__ void __launch_bounds__(256) k1_hmma_kernel(const float* __restrict__ Q) {
    extern __shared__ unsigned char dsm[];
    float* Afp  = (float*)dsm;                       /* [128][66] */
    float* s_qn = (float*)(dsm + 33792);
    float* s_ln = s_qn + 128;
    __nv_bfloat16* Bh = (__nv_bfloat16*)(dsm + 34816);   /* [64][66] */
    __nv_bfloat16* Bl = Bh + 64 * 66;

    int t = threadIdx.x, lane = t & 31, w = t >> 5;
    int bh = blockIdx.y, n0 = blockIdx.x * 128;

    {
        int row = t >> 1, kh = (t & 1) * 32;
        const float* qrow = Q + (size_t)bh * 262144 + (size_t)(n0 + row) * 64 + kh;
        float part = 0.f;
#pragma unroll
        for (int i = 0; i < 8; i++) {
            float4 v = *(const float4*)&qrow[i * 4];
            float x0 = v.x * SCALEF, x1 = v.y * SCALEF;
            float x2 = v.z * SCALEF, x3 = v.w * SCALEF;
            part += x0 * x0 + x1 * x1 + x2 * x2 + x3 * x3;
            float* dst = &Afp[row * 66 + kh + i * 4];
            *(float2*)dst       = make_float2(x0, x1);
            *(float2*)(dst + 2) = make_float2(x2, x3);
        }
        part += __shfl_xor_sync(0xffffffffu, part, 1);
        if ((t & 1) == 0) s_qn[row] = part;
        if (t < 128) s_ln[t] = g_ln[bh * 128 + t];
    }

    float* k1h = g_k1 + (size_t)bh * 524288 + (size_t)n0 * 128;
    int r0 = w * 16;
    int row0 = r0 + (lane >> 2);
    int kq = (lane & 3) * 2;

    for (int half = 0; half < 2; half++) {
        __syncthreads();
        {
            int mrow = t >> 2, ks = (t & 3) * 16;
            const float* lrow = g_QL + bh * 8192 + (size_t)(half * 64 + mrow) * 64 + ks;
            uint32_t* bhp = (uint32_t*)(Bh + mrow * 66 + ks);
            uint32_t* blp = (uint32_t*)(Bl + mrow * 66 + ks);
#pragma unroll
            for (int i = 0; i < 4; i++) {
                float4 v = *(const float4*)&lrow[i * 4];
                uint32_t h0, l0, h1, l1;
                split2(v.x, v.y, h0, l0);
                split2(v.z, v.w, h1, l1);
                bhp[i * 2] = h0; bhp[i * 2 + 1] = h1;
                blp[i * 2] = l0; blp[i * 2 + 1] = l1;
            }
        }
        __syncthreads();

        float acc[8][4];
#pragma unroll
        for (int i = 0; i < 8; i++)
#pragma unroll
            for (int j = 0; j < 4; j++) acc[i][j] = 0.f;

#pragma unroll
        for (int ks = 0; ks < 4; ks++) {
            int k0 = ks * 16 + kq;
            float2 v00 = *(const float2*)&Afp[row0 * 66 + k0];
            float2 v10 = *(const float2*)&Afp[(row0 + 8) * 66 + k0];
            float2 v01 = *(const float2*)&Afp[row0 * 66 + k0 + 8];
            float2 v11 = *(const float2*)&Afp[(row0 + 8) * 66 + k0 + 8];
            uint32_t ah0, al0, ah1, al1, ah2, al2, ah3, al3;
            split2(v00.x, v00.y, ah0, al0);
            split2(v10.x, v10.y, ah1, al1);
            split2(v01.x, v01.y, ah2, al2);
            split2(v11.x, v11.y, ah3, al3);
#pragma unroll
            for (int tile = 0; tile < 8; tile++) {
                int n = tile * 8 + (lane >> 2);
                const uint32_t* bhp = (const uint32_t*)(Bh + n * 66 + k0);
                const uint32_t* blp = (const uint32_t*)(Bl + n * 66 + k0);
                uint32_t bh0 = bhp[0], bh1 = bhp[4];
                uint32_t bl0 = blp[0], bl1 = blp[4];
                MMA_BF16(acc[tile], ah0, ah1, ah2, ah3, bh0, bh1);
                MMA_BF16(acc[tile], ah0, ah1, ah2, ah3, bl0, bl1);
                MMA_BF16(acc[tile], al0, al1, al2, al3, bh0, bh1);
            }
        }

        float qn0 = s_qn[row0], qn1 = s_qn[row0 + 8];
#pragma unroll
        for (int tile = 0; tile < 8; tile++) {
            int col = half * 64 + tile * 8 + kq;
            float l0 = s_ln[col], l1 = s_ln[col + 1];
            float d00 = fmaxf(qn0 + l0 - 2.0f * acc[tile][0], 0.f);
            float d01 = fmaxf(qn0 + l1 - 2.0f * acc[tile][1], 0.f);
            float d10 = fmaxf(qn1 + l0 - 2.0f * acc[tile][2], 0.f);
            float d11 = fmaxf(qn1 + l1 - 2.0f * acc[tile][3], 0.f);
            *(float2*)&k1h[(size_t)row0 * 128 + col] =
                make_float2(__expf(-0.5f * d00), __expf(-0.5f * d01));
            *(float2*)&k1h[(size_t)(row0 + 8) * 128 + col] =
                make_float2(__expf(-0.5f * d10), __expf(-0.5f * d11));
        }
    }
}

/* ------------------ 4. prep: rs, dg, cs via symmetry ------------------ */
__global__ void __launch_bounds__(128) prep_kernel() {
    extern __shared__ float Psh[];               /* [128][129] */
    __shared__ float rss[128];
    __shared__ float red[128];
    int bh = blockIdx.x, t = threadIdx.x;
    const float* Ph = g_P + bh * 16384;
    for (int i = t; i < 16384; i += 128) {
        int r = i >> 7, c = i & 127;
        Psh[r * 129 + c] = Ph[i];
    }
    __syncthreads();
    float rs = 0.f, dg = 0.f;
    for (int k = 0; k < 128; k++) {
        float v = Psh[t * 129 + k];
        rs += v; dg += v * v;
    }
    rss[t] = rs;
    g_dg[bh * 128 + t] = dg;
    red[t] = rs;
    __syncthreads();
    for (int st = 64; st; st >>= 1) {
        if (t < st) red[t] = fmaxf(red[t], red[t + st]);
        __syncthreads();
    }
    if (t == 0) atomicMax(&g_maxrs, __float_as_uint(red[0]));
    float cs = 0.f;
    for (int k = 0; k < 128; k++) cs += rss[k] * Psh[k * 129 + t];
    g_cs[bh * 128 + t] = cs;
}

/* ------------------ 4c. alpha init + 10 halvings (one block) ------------------ */
__global__ void alpha_kernel() {
    __shared__ float red[256];
    __shared__ float sh_alpha;
    int t = threadIdx.x;
    if (t == 0) {
        float mr = __uint_as_float(g_maxrs);
        sh_alpha = 2.0f / (mr * mr);
    }
    __syncthreads();
    for (int it = 0; it < 10; it++) {
        float a = sh_alpha;
        float mx = 0.f;
        for (int idx = t; idx < 4096; idx += 256) {
            float cs = g_cs[idx], dg = g_dg[idx];
            float v = a * (cs - dg) + fabsf(1.0f - a * dg);
            mx = fmaxf(mx, v);
        }
        red[t] = mx;
        __syncthreads();
        for (int st = 128; st; st >>= 1) {
            if (t < st) red[t] = fmaxf(red[t], red[t + st]);
            __syncthreads();
        }
        if (t == 0 && red[0] > 1.01f) sh_alpha = a * 0.5f;
        __syncthreads();
    }
    if (t == 0) { g_alpha = sh_alpha; g_done = 0; g_maxc = 0u; g_cur = 0; }
}

/* ------------------ 4d. VmA = alpha * P ------------------ */
__global__ void vminit_kernel() {
    int i = blockIdx.x * 256 + threadIdx.x;
    float a = g_alpha;
    float4 p = ((const float4*)g_P)[i];
    ((float4*)g_VmA)[i] = make_float4(a * p.x, a * p.y, a * p.z, a * p.w);
}

/* ------------------ 5. persistent Newton via HMMA; decide fused into barrier ------------------ */
__global__ void __launch_bounds__(256, 1) newton_persistent() {
    extern __shared__ unsigned char dsm[];
    uint32_t* Phu = (uint32_t*)dsm;          /* [128][66] u32 */
    uint32_t* Plu = Phu + 8448;
    uint32_t* Vhu = Phu + 16896;
    uint32_t* Vlu = Phu + 25344;
    uint32_t* Thu = Phu + 33792;             /* [32][66] */
    uint32_t* Tlu = Phu + 35904;             /* total 38016 u32 = 152064 B */
    __shared__ float red[256];

    int t = threadIdx.x, lane = t & 31, w = t >> 5;
    int wr = w >> 2, wc = w & 3;
    int g = lane >> 2, tq = lane & 3;
    int bh = blockIdx.x >> 2;
    int r0 = (blockIdx.x & 3) * 32;
    const float* Pg = g_P + bh * 16384;

    split_tile_128(Pg, Phu, Plu, t);

    for (int it = 0; it < 20; it++) {
        if (!(*(volatile int*)&g_done)) {
            int cur = *(volatile int*)&g_cur;
            const float* Vmg = (cur ? g_VmB : g_VmA) + bh * 16384;
            float*       Cg  = (cur ? g_VmA : g_VmB) + bh * 16384;
            __syncthreads();
            split_tile_128(Vmg, Vhu, Vlu, t);
            __syncthreads();

            float acc[4][4];
#pragma unroll
            for (int i = 0; i < 4; i++)
#pragma unroll
                for (int j = 0; j < 4; j++) acc[i][j] = 0.f;
            int rA = r0 + wr * 16 + g;
#pragma unroll
            for (int ks = 0; ks < 8; ks++) {
                int ko = ks * 8 + tq;
                uint32_t ah0 = Vhu[rA * 66 + ko],        ah1 = Vhu[(rA + 8) * 66 + ko];
                uint32_t ah2 = Vhu[rA * 66 + ko + 4],    ah3 = Vhu[(rA + 8) * 66 + ko + 4];
                uint32_t al0 = Vlu[rA * 66 + ko],        al1 = Vlu[(rA + 8) * 66 + ko];
                uint32_t al2 = Vlu[rA * 66 + ko + 4],    al3 = Vlu[(rA + 8) * 66 + ko + 4];
#pragma unroll
                for (int tile = 0; tile < 4; tile++) {
                    int n = wc * 32 + tile * 8 + g;
                    uint32_t bh0 = Phu[n * 66 + ko], bh1 = Phu[n * 66 + ko + 4];
                    uint32_t bl0 = Plu[n * 66 + ko], bl1 = Plu[n * 66 + ko + 4];
                    MMA_BF16(acc[tile], ah0, ah1, ah2, ah3, bh0, bh1);
                    MMA_BF16(acc[tile], ah0, ah1, ah2, ah3, bl0, bl1);
                    MMA_BF16(acc[tile], al0, al1, al2, al3, bh0, bh1);
                }
            }
            int trl = wr * 16 + g;
#pragma unroll
            for (int tile = 0; tile < 4; tile++) {
                int c2 = wc * 16 + tile * 4 + tq;
                uint32_t h, l;
                split2(acc[tile][0], acc[tile][1], h, l);
                Thu[trl * 66 + c2] = h; Tlu[trl * 66 + c2] = l;
                split2(acc[tile][2], acc[tile][3], h, l);
                Thu[(trl + 8) * 66 + c2] = h; Tlu[(trl + 8) * 66 + c2] = l;
            }
            __syncthreads();

#pragma unroll
            for (int i = 0; i < 4; i++)
#pragma unroll
                for (int j = 0; j < 4; j++) acc[i][j] = 0.f;
#pragma unroll
            for (int ks = 0; ks < 8; ks++) {
                int ko = ks * 8 + tq;
                uint32_t ah0 = Thu[trl * 66 + ko],       ah1 = Thu[(trl + 8) * 66 + ko];
                uint32_t ah2 = Thu[trl * 66 + ko + 4],   ah3 = Thu[(trl + 8) * 66 + ko + 4];
                uint32_t al0 = Tlu[trl * 66 + ko],       al1 = Tlu[(trl + 8) * 66 + ko];
                uint32_t al2 = Tlu[trl * 66 + ko + 4],   al3 = Tlu[(trl + 8) * 66 + ko + 4];
#pragma unroll
                for (int tile = 0; tile < 4; tile++) {
                    int n = wc * 32 + tile * 8 + g;
                    uint32_t bh0 = Vhu[n * 66 + ko], bh1 = Vhu[n * 66 + ko + 4];
                    uint32_t bl0 = Vlu[n * 66 + ko], bl1 = Vlu[n * 66 + ko + 4];
                    MMA_BF16(acc[tile], ah0, ah1, ah2, ah3, bh0, bh1);
                    MMA_BF16(acc[tile], ah0, ah1, ah2, ah3, bl0, bl1);
                    MMA_BF16(acc[tile], al0, al1, al2, al3, bh0, bh1);
                }
            }
            float mx = 0.f;
            int rowg = r0 + wr * 16 + g;
#pragma unroll
            for (int tile = 0; tile < 4; tile++) {
                int c = wc * 32 + tile * 8 + 2 * tq;
                float2 vm0 = *(const float2*)&Vmg[rowg * 128 + c];
                float2 vm1 = *(const float2*)&Vmg[(rowg + 8) * 128 + c];
                float o0 = 2.0f * vm0.x - acc[tile][0];
                float o1 = 2.0f * vm0.y - acc[tile][1];
                float o2 = 2.0f * vm1.x - acc[tile][2];
                float o3 = 2.0f * vm1.y - acc[tile][3];
                mx = fmaxf(mx, fmaxf(fmaxf(fabsf(o0), fabsf(o1)),
                                     fmaxf(fabsf(o2), fabsf(o3))));
                *(float2*)&Cg[rowg * 128 + c]       = make_float2(o0, o1);
                *(float2*)&Cg[(rowg + 8) * 128 + c] = make_float2(o2, o3);
            }
            red[t] = mx;
            __syncthreads();
            for (int st = 128; st; st >>= 1) {
                if (t < st) red[t] = fmaxf(red[t], red[t + st]);
                __syncthreads();
            }
            if (t == 0) atomicMax(&g_maxc, __float_as_uint(red[0]));
        }
        /* merged barrier: last-arriving block performs the decide before release */
        __syncthreads();
        if (t == 0) {
            __threadfence();
            int gen = *(volatile int*)&g_bar_gen;
            if (atomicAdd(&g_bar_count, 1) == NBLK - 1) {
                g_bar_count = 0;
                if (!g_done) {
                    float m = __uint_as_float(g_maxc);
                    if (m > 10000.0f) g_done = 1;
                    else              g_cur ^= 1;
                    g_maxc = 0u;
                }
                __threadfence();
                *(volatile int*)&g_bar_gen = gen + 1;
            } else {
                while (*(volatile int*)&g_bar_gen == gen) __nanosleep(32);
            }
        }
        __syncthreads();
    }
}

/* ------------------ 6. kv partials: kv = k1^T @ V, split-K over n (FFMA) ------------------ */
__global__ void kv_kernel(const float* __restrict__ V) {
    __shared__ float Ks[32][132];
    __shared__ float Vs[32][68];
    int c = blockIdx.x, bh = blockIdx.y;
    int t = threadIdx.x, tx = t & 15, ty = t >> 4;
    const float* k1h = g_k1 + (size_t)bh * 524288;
    const float* Vh = V + (size_t)bh * 262144;
    float acc[8][4];
#pragma unroll
    for (int i = 0; i < 8; i++)
#pragma unroll
        for (int j = 0; j < 4; j++) acc[i][j] = 0.f;
    for (int sc = 0; sc < 256; sc += 32) {
        int nb = c * 256 + sc;
        for (int idx = t; idx < 4096; idx += 256) {
            int n = idx >> 7, m = idx & 127;
            Ks[n][m] = k1h[(size_t)(nb + n) * 128 + m];
        }
        for (int idx = t; idx < 2048; idx += 256) {
            int n = idx >> 6, d = idx & 63;
            Vs[n][d] = Vh[(size_t)(nb + n) * 64 + d];
        }
        __syncthreads();
#pragma unroll 4
        for (int n = 0; n < 32; n++) {
            float4 a0 = *(const float4*)&Ks[n][ty * 8];
            float4 a1 = *(const float4*)&Ks[n][ty * 8 + 4];
            float4 b = *(const float4*)&Vs[n][tx * 4];
            float a[8] = {a0.x,a0.y,a0.z,a0.w,a1.x,a1.y,a1.z,a1.w};
#pragma unroll
            for (int i = 0; i < 8; i++) {
                acc[i][0] += a[i] * b.x; acc[i][1] += a[i] * b.y;
                acc[i][2] += a[i] * b.z; acc[i][3] += a[i] * b.w;
            }
        }
        __syncthreads();
    }
    float* kvp = g_kvp + (size_t)(c * 32 + bh) * 8192;
#pragma unroll
    for (int i = 0; i < 8; i++)
        *(float4*)&kvp[(ty * 8 + i) * 64 + tx * 4] =
            make_float4(acc[i][0], acc[i][1], acc[i][2], acc[i][3]);
}

__global__ void kvreduce_kernel() {
    int o = blockIdx.x * 256 + threadIdx.x;
    float s = 0.f;
    for (int c = 0; c < 16; c++) s += g_kvp[(size_t)c * 262144 + o];
    g_kv[o] = s;
}

/* ------------------ 6b. Tm = Vm @ kv ------------------ */
__global__ void mm_tm() {
    const float* A = (*(volatile int*)&g_cur) ? g_VmB : g_VmA;
    int bh = blockIdx.y;
    int tm = blockIdx.x * 64;
    const float* Ah = A + bh * 16384;
    const float* Bh = g_kv + bh * 8192;
    float* Ch = g_Tm + bh * 8192;
    __shared__ float At[16][68], Bt[16][68];
    int t = threadIdx.x, tx = t & 15, ty = t >> 4;
    float acc[4][4];
#pragma unroll
    for (int i = 0; i < 4; i++)
#pragma unroll
        for (int j = 0; j < 4; j++) acc[i][j] = 0.f;
    for (int kc = 0; kc < 128; kc += 16) {
        {
            int r = t >> 2, kq = (t & 3) << 2;
            float4 v = *(const float4*)&Ah[(tm + r) * 128 + kc + kq];
            At[kq + 0][r] = v.x; At[kq + 1][r] = v.y;
            At[kq + 2][r] = v.z; At[kq + 3][r] = v.w;
        }
        {
            int k = t >> 4, cq = (t & 15) << 2;
            if (cq < 64)
                *(float4*)&Bt[k][cq] = *(const float4*)&Bh[(kc + k) * 64 + cq];
        }
        __syncthreads();
#pragma unroll
        for (int k = 0; k < 16; k++) {
            float4 av = *(const float4*)&At[k][ty * 4];
            float4 bv = *(const float4*)&Bt[k][tx * 4];
            float a[4] = {av.x, av.y, av.z, av.w};
            float b[4] = {bv.x, bv.y, bv.z, bv.w};
#pragma unroll
            for (int i = 0; i < 4; i++)
#pragma unroll
                for (int j = 0; j < 4; j++) acc[i][j] += a[i] * b[j];
        }
        __syncthreads();
    }
#pragma unroll
    for (int i = 0; i < 4; i++) {
        int row = tm + ty * 4 + i;
        *(float4*)&Ch[row * 64 + tx * 4] =
            make_float4(acc[i][0], acc[i][1], acc[i][2], acc[i][3]);
    }
}

/* ------------------ 7. final via HMMA: X = k1 @ Tm + depthwise conv(V) ------------------ */
__global__ void __launch_bounds__(256) final_hmma_kernel(const float* __restrict__ V,
                                                         const float* __restrict__ cw,
                                                         float* __restrict__ out) {
    extern __shared__ unsigned char dsm[];
    uint32_t* K1hu  = (uint32_t*)dsm;        /* [128][66] u32 */
    uint32_t* K1lu  = K1hu + 8448;
    uint32_t* TmThu = K1hu + 16896;          /* [64][66] u32 : TmT[d][m] */
    uint32_t* TmTlu = K1hu + 21120;          /* total 25344 u32 = 101376 B */

    int t = threadIdx.x, lane = t & 31, w = t >> 5;
    int g = lane >> 2, tq = lane & 3;
    int bh = blockIdx.y, n0 = blockIdx.x * 128;
    const float* k1g = g_k1 + (size_t)bh * 524288 + (size_t)n0 * 128;
    const float* Tmg = g_Tm + bh * 8192;

    split_tile_128(k1g, K1hu, K1lu, t);
    for (int i = t; i < 4096; i += 256) {
        int d = i >> 6, mp = i & 63;
        float x = Tmg[(2 * mp) * 64 + d];
        float y = Tmg[(2 * mp + 1) * 64 + d];
        uint32_t h, l;
        split2(x, y, h, l);
        TmThu[d * 66 + mp] = h;
        TmTlu[d * 66 + mp] = l;
    }
    __syncthreads();

    float acc[8][4];
#pragma unroll
    for (int i = 0; i < 8; i++)
#pragma unroll
        for (int j = 0; j < 4; j++) acc[i][j] = 0.f;
    int rA = w * 16 + g;
#pragma unroll
    for (int ks = 0; ks < 8; ks++) {
        int ko = ks * 8 + tq;
        uint32_t ah0 = K1hu[rA * 66 + ko],       ah1 = K1hu[(rA + 8) * 66 + ko];
        uint32_t ah2 = K1hu[rA * 66 + ko + 4],   ah3 = K1hu[(rA + 8) * 66 + ko + 4];
        uint32_t al0 = K1lu[rA * 66 + ko],       al1 = K1lu[(rA + 8) * 66 + ko];
        uint32_t al2 = K1lu[rA * 66 + ko + 4],   al3 = K1lu[(rA + 8) * 66 + ko + 4];
#pragma unroll
        for (int tile = 0; tile < 8; tile++) {
            int n = tile * 8 + g;
            uint32_t bh0 = TmThu[n * 66 + ko], bh1 = TmThu[n * 66 + ko + 4];
            uint32_t bl0 = TmTlu[n * 66 + ko], bl1 = TmTlu[n * 66 + ko + 4];
            MMA_BF16(acc[tile], ah0, ah1, ah2, ah3, bh0, bh1);
            MMA_BF16(acc[tile], ah0, ah1, ah2, ah3, bl0, bl1);
            MMA_BF16(acc[tile], al0, al1, al2, al3, bh0, bh1);
        }
    }

    int h = bh & 15;
    float w0 = cw[h * 3], w1 = cw[h * 3 + 1], w2 = cw[h * 3 + 2];
    const float* Vh = V + (size_t)bh * 262144;
    float* oh = out + (size_t)bh * 262144;
#pragma unroll
    for (int tile = 0; tile < 8; tile++) {
        int d = tile * 8 + 2 * tq;
#pragma unroll
        for (int rr = 0; rr < 2; rr++) {
            int n = n0 + w * 16 + g + rr * 8;
            float a0 = acc[tile][rr * 2], a1 = acc[tile][rr * 2 + 1];
            float2 vc = *(const float2*)&Vh[(size_t)n * 64 + d];
            float2 vp = (n > 0)    ? *(const float2*)&Vh[(size_t)(n - 1) * 64 + d] : make_float2(0.f, 0.f);
            float2 vn = (n < 4095) ? *(const float2*)&Vh[(size_t)(n + 1) * 64 + d] : make_float2(0.f, 0.f);
            float2 o;
            o.x = a0 + w0 * vp.x + w1 * vc.x + w2 * vn.x;
            o.y = a1 + w0 * vp.y + w1 * vc.y + w2 * vn.y;
            *(float2*)&oh[(size_t)n * 64 + d] = o;
        }
    }
}

/* ------------------ launch ------------------ */
extern "C" void kernel_launch(void* const* d_in, const int* in_sizes, int n_in,
                              void* d_out, int out_size) {
    (void)in_sizes; (void)n_in; (void)out_size;
    const float* Q     = (const float*)d_in[0];
    const float* V     = (const float*)d_in[1];
    const float* Wland = (const float*)d_in[2];
    const float* gamma = (const float*)d_in[3];
    const float* beta  = (const float*)d_in[4];
    const float* convw = (const float*)d_in[5];
    float* out = (float*)d_out;

    cudaFuncSetAttribute(k1_hmma_kernel,
                         cudaFuncAttributeMaxDynamicSharedMemorySize, 52224);
    cudaFuncSetAttribute(newton_persistent,
                         cudaFuncAttributeMaxDynamicSharedMemorySize, 152064);
    cudaFuncSetAttribute(final_hmma_kernel,
                         cudaFuncAttributeMaxDynamicSharedMemorySize, 101376);
    cudaFuncSetAttribute(prep_kernel,
                         cudaFuncAttributeMaxDynamicSharedMemorySize, 66048);

    wtrans_kernel<<<512, 256>>>(Wland);
    landmark_kernel<<<dim3(4, BH), 256>>>(Q, gamma, beta);
    k2_kernel<<<BH, 256>>>();
    k1_hmma_kernel<<<dim3(32, BH), 256, 51712>>>(Q);
    prep_kernel<<<BH, 128, 66048>>>();
    alpha_kernel<<<1, 256>>>();
    vminit_kernel<<<512, 256>>>();
    newton_persistent<<<NBLK, 256, 152064>>>();
    kv_kernel<<<dim3(16, BH), 256>>>(V);
    kvreduce_kernel<<<1024, 256>>>();
    mm_tm<<<dim3(2, BH), 256>>>();
    final_hmma_kernel<<<dim3(32, BH), 256, 101376>>>(V, convw, out);
}

// round 14
// speedup vs baseline: 1.0782x; 1.0181x over previous
#include <cuda_runtime.h>
#include <cuda_bf16.h>
#include <math.h>
#include <stdint.h>

#define BH     32
#define NSEQ   4096
#define DDIM   64
#define MLAND  128
#define NBLK   128
#define SCALEF 0.3535533905932738f   /* 64^-0.25 */

/* ------------------ scratch: __device__ globals (no allocs) ------------------ */
__device__ __align__(16) float g_Wt[2048 * 64];
__device__ __align__(16) float g_QL[BH * MLAND * DDIM];
__device__ __align__(16) float g_ln[BH * MLAND];
__device__ __align__(16) float g_P [BH * MLAND * MLAND];
__device__ __align__(16) float g_VmA[BH * MLAND * MLAND];
__device__ __align__(16) float g_VmB[BH * MLAND * MLAND];
__device__ __align__(16) float g_cs[BH * MLAND];
__device__ __align__(16) float g_dg[BH * MLAND];
__device__ __align__(16) float g_kv [BH * MLAND * DDIM];
__device__ __align__(16) float g_kvp[16 * BH * MLAND * DDIM];
__device__ __align__(16) float g_Tm[BH * MLAND * DDIM];
__device__ __align__(16) float g_k1[(size_t)BH * NSEQ * MLAND]; /* 64 MB */
__device__ float    g_alpha;
__device__ unsigned g_maxrs;
__device__ unsigned g_maxc;
__device__ int      g_done;
__device__ int      g_cur;
__device__ int      g_bar_count;
__device__ int      g_bar_gen;

__device__ __forceinline__ uint32_t pack_bf2(__nv_bfloat16 a, __nv_bfloat16 b) {
    return (uint32_t)__bfloat16_as_ushort(a) | ((uint32_t)__bfloat16_as_ushort(b) << 16);
}
__device__ __forceinline__ void split2(float x, float y, uint32_t& hi, uint32_t& lo) {
    __nv_bfloat16 hx = __float2bfloat16(x), hy = __float2bfloat16(y);
    hi = pack_bf2(hx, hy);
    lo = pack_bf2(__float2bfloat16(x - __bfloat162float(hx)),
                  __float2bfloat16(y - __bfloat162float(hy)));
}
#define MMA_BF16(c, a0, a1, a2, a3, b0, b1)                                  \
    asm volatile("mma.sync.aligned.m16n8k16.row.col.f32.bf16.bf16.f32 "      \
        "{%0,%1,%2,%3}, {%4,%5,%6,%7}, {%8,%9}, {%0,%1,%2,%3};"              \
        : "+f"((c)[0]), "+f"((c)[1]), "+f"((c)[2]), "+f"((c)[3])             \
        : "r"(a0), "r"(a1), "r"(a2), "r"(a3), "r"(b0), "r"(b1))

/* split 128x128 fp32 (global, row stride 128) -> hi/lo u32 smem (row stride 66) */
__device__ __forceinline__ void split_tile_128(const float* __restrict__ g,
                                               uint32_t* hi, uint32_t* lo, int t) {
    for (int i = t; i < 8192; i += 256) {
        float2 v = ((const float2*)g)[i];
        uint32_t h, l;
        split2(v.x, v.y, h, l);
        int row = i >> 6, cp = i & 63;
        hi[row * 66 + cp] = h;
        lo[row * 66 + cp] = l;
    }
}

/* ------------------ 0. weight relayout (+ reset g_maxrs) ------------------ */
__global__ void wtrans_kernel(const float* __restrict__ W) {
    int idx = blockIdx.x * 256 + threadIdx.x;
    if (idx == 0) g_maxrs = 0u;
    int o = idx >> 11, i = (idx >> 5) & 63, k = idx & 31;
    g_Wt[(k * 64 + i) * 64 + o] = W[idx];
}

/* ------------------ 1. landmarks: GEMM + LayerNorm + exact GELU ------------------ */
__global__ void landmark_kernel(const float* __restrict__ Q,
                                const float* __restrict__ gamma,
                                const float* __restrict__ beta) {
    __shared__ float As[32][68];
    __shared__ float Ws[64][68];
    __shared__ float S[32][65];
    int bh = blockIdx.y, mb = blockIdx.x;
    int t = threadIdx.x;
    int tx = t & 63, ty = t >> 6;
    const float* qbase = Q + (size_t)bh * 262144 + (size_t)mb * 65536;
    float acc[8] = {0.f,0.f,0.f,0.f,0.f,0.f,0.f,0.f};
    for (int kc = 0; kc < 2048; kc += 64) {
        for (int idx = t; idx < 2048; idx += 256) {
            int r = idx >> 6, k = idx & 63;
            As[r][k] = qbase[r * 2048 + kc + k] * SCALEF;
        }
        for (int idx = t; idx < 4096; idx += 256) {
            int o = idx & 63, k = idx >> 6;
            Ws[o][k] = g_Wt[(kc + k) * 64 + o];
        }
        __syncthreads();
#pragma unroll
        for (int k4 = 0; k4 < 64; k4 += 4) {
            float4 w = *(const float4*)&Ws[tx][k4];
#pragma unroll
            for (int j = 0; j < 8; j++) {
                float4 a = *(const float4*)&As[ty * 8 + j][k4];
                acc[j] += a.x * w.x + a.y * w.y + a.z * w.z + a.w * w.w;
            }
        }
        __syncthreads();
    }
#pragma unroll
    for (int j = 0; j < 8; j++) S[ty * 8 + j][tx] = acc[j];
    __syncthreads();
    int warp = t >> 5, lane = t & 31;
    for (int rr = 0; rr < 4; rr++) {
        int row = warp * 4 + rr;
        float x0 = S[row][lane], x1 = S[row][lane + 32];
        float s = x0 + x1;
#pragma unroll
        for (int off = 16; off; off >>= 1) s += __shfl_xor_sync(0xffffffffu, s, off);
        float mu = s * (1.0f / 64.0f);
        float d0 = x0 - mu, d1 = x1 - mu;
        float v = d0 * d0 + d1 * d1;
#pragma unroll
        for (int off = 16; off; off >>= 1) v += __shfl_xor_sync(0xffffffffu, v, off);
        float rstd = rsqrtf(v * (1.0f / 64.0f) + 1e-5f);
        int mg = bh * 128 + mb * 32 + row;
#pragma unroll
        for (int cc = 0; cc < 2; cc++) {
            int c = lane + cc * 32;
            float x = cc ? x1 : x0;
            float y = (x - mu) * rstd * gamma[c] + beta[c];
            float g = 0.5f * y * (1.0f + erff(y * 0.70710678118654752f));
            g_QL[mg * 64 + c] = g;
        }
    }
}

/* ------------------ 2. P = k2 = exp(-0.5 sqdist(QL,QL)) ------------------ */
__global__ void k2_kernel() {
    __shared__ float QLt[64][132];
    __shared__ float lnorm[128];
    int bh = blockIdx.x, t = threadIdx.x;
    const float* ql = g_QL + bh * 8192;
    for (int idx = t; idx < 8192; idx += 256) {
        int m = idx >> 6, k = idx & 63;
        QLt[k][m] = ql[idx];
    }
    __syncthreads();
    if (t < 128) {
        float s = 0.f;
        for (int k = 0; k < 64; k++) { float v = QLt[k][t]; s += v * v; }
        lnorm[t] = s;
        g_ln[bh * 128 + t] = s;
    }
    __syncthreads();
    int tx = t & 15, ty = t >> 4;
    float acc[8][8];
#pragma unroll
    for (int i = 0; i < 8; i++)
#pragma unroll
        for (int j = 0; j < 8; j++) acc[i][j] = 0.f;
#pragma unroll 4
    for (int k = 0; k < 64; k++) {
        float4 a0 = *(const float4*)&QLt[k][ty * 8];
        float4 a1 = *(const float4*)&QLt[k][ty * 8 + 4];
        float4 b0 = *(const float4*)&QLt[k][tx * 8];
        float4 b1 = *(const float4*)&QLt[k][tx * 8 + 4];
        float a[8] = {a0.x,a0.y,a0.z,a0.w,a1.x,a1.y,a1.z,a1.w};
        float b[8] = {b0.x,b0.y,b0.z,b0.w,b1.x,b1.y,b1.z,b1.w};
#pragma unroll
        for (int i = 0; i < 8; i++)
#pragma unroll
            for (int j = 0; j < 8; j++) acc[i][j] += a[i] * b[j];
    }
    float* Ph = g_P + bh * 16384;
#pragma unroll
    for (int i = 0; i < 8; i++) {
        int m = ty * 8 + i;
        float o[8];
#pragma unroll
        for (int j = 0; j < 8; j++) {
            float d = lnorm[m] + lnorm[tx * 8 + j] - 2.0f * acc[i][j];
            d = fmaxf(d, 0.0f);
            o[j] = expf(-0.5f * d);
        }
        *(float4*)&Ph[m * 128 + tx * 8]     = make_float4(o[0], o[1], o[2], o[3]);
        *(float4*)&Ph[m * 128 + tx * 8 + 4] = make_float4(o[4], o[5], o[6], o[7]);
    }
}

/* ------------------ 3. k1 via mma.sync (HMMA) bf16-split, 3-pass ------------------ */
__global__ void __launch_bounds__(256) k1_hmma_kernel(const float* __restrict__ Q) {
    extern __shared__ unsigned char dsm[];
    float* Afp  = (float*)dsm;                       /* [128][66] */
    float* s_qn = (float*)(dsm + 33792);
    float* s_ln = s_qn + 128;
    __nv_bfloat16* Bh = (__nv_bfloat16*)(dsm + 34816);   /* [64][66] */
    __nv_bfloat16* Bl = Bh + 64 * 66;

    int t = threadIdx.x, lane = t & 31, w = t >> 5;
    int bh = blockIdx.y, n0 = blockIdx.x * 128;

    {
        int row = t >> 1, kh = (t & 1) * 32;
        const float* qrow = Q + (size_t)bh * 262144 + (size_t)(n0 + row) * 64 + kh;
        float part = 0.f;
#pragma unroll
        for (int i = 0; i < 8; i++) {
            float4 v = *(const float4*)&qrow[i * 4];
            float x0 = v.x * SCALEF, x1 = v.y * SCALEF;
            float x2 = v.z * SCALEF, x3 = v.w * SCALEF;
            part += x0 * x0 + x1 * x1 + x2 * x2 + x3 * x3;
            float* dst = &Afp[row * 66 + kh + i * 4];
            *(float2*)dst       = make_float2(x0, x1);
            *(float2*)(dst + 2) = make_float2(x2, x3);
        }
        part += __shfl_xor_sync(0xffffffffu, part, 1);
        if ((t & 1) == 0) s_qn[row] = part;
        if (t < 128) s_ln[t] = g_ln[bh * 128 + t];
    }

    float* k1h = g_k1 + (size_t)bh * 524288 + (size_t)n0 * 128;
    int r0 = w * 16;
    int row0 = r0 + (lane >> 2);
    int kq = (lane & 3) * 2;

    for (int half = 0; half < 2; half++) {
        __syncthreads();
        {
            int mrow = t >> 2, ks = (t & 3) * 16;
            const float* lrow = g_QL + bh * 8192 + (size_t)(half * 64 + mrow) * 64 + ks;
            uint32_t* bhp = (uint32_t*)(Bh + mrow * 66 + ks);
            uint32_t* blp = (uint32_t*)(Bl + mrow * 66 + ks);
#pragma unroll
            for (int i = 0; i < 4; i++) {
                float4 v = *(const float4*)&lrow[i * 4];
                uint32_t h0, l0, h1, l1;
                split2(v.x, v.y, h0, l0);
                split2(v.z, v.w, h1, l1);
                bhp[i * 2] = h0; bhp[i * 2 + 1] = h1;
                blp[i * 2] = l0; blp[i * 2 + 1] = l1;
            }
        }
        __syncthreads();

        float acc[8][4];
#pragma unroll
        for (int i = 0; i < 8; i++)
#pragma unroll
            for (int j = 0; j < 4; j++) acc[i][j] = 0.f;

#pragma unroll
        for (int ks = 0; ks < 4; ks++) {
            int k0 = ks * 16 + kq;
            float2 v00 = *(const float2*)&Afp[row0 * 66 + k0];
            float2 v10 = *(const float2*)&Afp[(row0 + 8) * 66 + k0];
            float2 v01 = *(const float2*)&Afp[row0 * 66 + k0 + 8];
            float2 v11 = *(const float2*)&Afp[(row0 + 8) * 66 + k0 + 8];
            uint32_t ah0, al0, ah1, al1, ah2, al2, ah3, al3;
            split2(v00.x, v00.y, ah0, al0);
            split2(v10.x, v10.y, ah1, al1);
            split2(v01.x, v01.y, ah2, al2);
            split2(v11.x, v11.y, ah3, al3);
#pragma unroll
            for (int tile = 0; tile < 8; tile++) {
                int n = tile * 8 + (lane >> 2);
                const uint32_t* bhp = (const uint32_t*)(Bh + n * 66 + k0);
                const uint32_t* blp = (const uint32_t*)(Bl + n * 66 + k0);
                uint32_t bh0 = bhp[0], bh1 = bhp[4];
                uint32_t bl0 = blp[0], bl1 = blp[4];
                MMA_BF16(acc[tile], ah0, ah1, ah2, ah3, bh0, bh1);
                MMA_BF16(acc[tile], ah0, ah1, ah2, ah3, bl0, bl1);
                MMA_BF16(acc[tile], al0, al1, al2, al3, bh0, bh1);
            }
        }

        float qn0 = s_qn[row0], qn1 = s_qn[row0 + 8];
#pragma unroll
        for (int tile = 0; tile < 8; tile++) {
            int col = half * 64 + tile * 8 + kq;
            float l0 = s_ln[col], l1 = s_ln[col + 1];
            float d00 = fmaxf(qn0 + l0 - 2.0f * acc[tile][0], 0.f);
            float d01 = fmaxf(qn0 + l1 - 2.0f * acc[tile][1], 0.f);
            float d10 = fmaxf(qn1 + l0 - 2.0f * acc[tile][2], 0.f);
            float d11 = fmaxf(qn1 + l1 - 2.0f * acc[tile][3], 0.f);
            *(float2*)&k1h[(size_t)row0 * 128 + col] =
                make_float2(__expf(-0.5f * d00), __expf(-0.5f * d01));
            *(float2*)&k1h[(size_t)(row0 + 8) * 128 + col] =
                make_float2(__expf(-0.5f * d10), __expf(-0.5f * d11));
        }
    }
}

/* ------------------ 4. prep: rs, dg, cs via symmetry ------------------ */
__global__ void __launch_bounds__(128) prep_kernel() {
    extern __shared__ float Psh[];               /* [128][129] */
    __shared__ float rss[128];
    __shared__ float red[128];
    int bh = blockIdx.x, t = threadIdx.x;
    const float* Ph = g_P + bh * 16384;
    for (int i = t; i < 16384; i += 128) {
        int r = i >> 7, c = i & 127;
        Psh[r * 129 + c] = Ph[i];
    }
    __syncthreads();
    float rs = 0.f, dg = 0.f;
    for (int k = 0; k < 128; k++) {
        float v = Psh[t * 129 + k];
        rs += v; dg += v * v;
    }
    rss[t] = rs;
    g_dg[bh * 128 + t] = dg;
    red[t] = rs;
    __syncthreads();
    for (int st = 64; st; st >>= 1) {
        if (t < st) red[t] = fmaxf(red[t], red[t + st]);
        __syncthreads();
    }
    if (t == 0) atomicMax(&g_maxrs, __float_as_uint(red[0]));
    float cs = 0.f;
    for (int k = 0; k < 128; k++) cs += rss[k] * Psh[k * 129 + t];
    g_cs[bh * 128 + t] = cs;
}

/* ------------------ 4c. alpha init + 10 halvings (one block) ------------------ */
__global__ void alpha_kernel() {
    __shared__ float red[256];
    __shared__ float sh_alpha;
    int t = threadIdx.x;
    if (t == 0) {
        float mr = __uint_as_float(g_maxrs);
        sh_alpha = 2.0f / (mr * mr);
    }
    __syncthreads();
    for (int it = 0; it < 10; it++) {
        float a = sh_alpha;
        float mx = 0.f;
        for (int idx = t; idx < 4096; idx += 256) {
            float cs = g_cs[idx], dg = g_dg[idx];
            float v = a * (cs - dg) + fabsf(1.0f - a * dg);
            mx = fmaxf(mx, v);
        }
        red[t] = mx;
        __syncthreads();
        for (int st = 128; st; st >>= 1) {
            if (t < st) red[t] = fmaxf(red[t], red[t + st]);
            __syncthreads();
        }
        if (t == 0 && red[0] > 1.01f) sh_alpha = a * 0.5f;
        __syncthreads();
    }
    if (t == 0) { g_alpha = sh_alpha; g_done = 0; g_maxc = 0u; g_cur = 0; }
}

/* ------------------ 4d. VmA = alpha * P ------------------ */
__global__ void vminit_kernel() {
    int i = blockIdx.x * 256 + threadIdx.x;
    float a = g_alpha;
    float4 p = ((const float4*)g_P)[i];
    ((float4*)g_VmA)[i] = make_float4(a * p.x, a * p.y, a * p.z, a * p.w);
}

/* ------------------ 5. persistent Newton via HMMA; decide fused into barrier ------------------ */
__global__ void __launch_bounds__(256, 1) newton_persistent() {
    extern __shared__ unsigned char dsm[];
    uint32_t* Phu = (uint32_t*)dsm;          /* [128][66] u32 */
    uint32_t* Plu = Phu + 8448;
    uint32_t* Vhu = Phu + 16896;
    uint32_t* Vlu = Phu + 25344;
    uint32_t* Thu = Phu + 33792;             /* [32][66] */
    uint32_t* Tlu = Phu + 35904;             /* total 38016 u32 = 152064 B */
    __shared__ float red[256];

    int t = threadIdx.x, lane = t & 31, w = t >> 5;
    int wr = w >> 2, wc = w & 3;
    int g = lane >> 2, tq = lane & 3;
    int bh = blockIdx.x >> 2;
    int r0 = (blockIdx.x & 3) * 32;
    const float* Pg = g_P + bh * 16384;

    split_tile_128(Pg, Phu, Plu, t);

    for (int it = 0; it < 20; it++) {
        if (!(*(volatile int*)&g_done)) {
            int cur = *(volatile int*)&g_cur;
            const float* Vmg = (cur ? g_VmB : g_VmA) + bh * 16384;
            float*       Cg  = (cur ? g_VmA : g_VmB) + bh * 16384;
            __syncthreads();
            split_tile_128(Vmg, Vhu, Vlu, t);
            __syncthreads();

            float acc[4][4];
#pragma unroll
            for (int i = 0; i < 4; i++)
#pragma unroll
                for (int j = 0; j < 4; j++) acc[i][j] = 0.f;
            int rA = r0 + wr * 16 + g;
#pragma unroll
            for (int ks = 0; ks < 8; ks++) {
                int ko = ks * 8 + tq;
                uint32_t ah0 = Vhu[rA * 66 + ko],        ah1 = Vhu[(rA + 8) * 66 + ko];
                uint32_t ah2 = Vhu[rA * 66 + ko + 4],    ah3 = Vhu[(rA + 8) * 66 + ko + 4];
                uint32_t al0 = Vlu[rA * 66 + ko],        al1 = Vlu[(rA + 8) * 66 + ko];
                uint32_t al2 = Vlu[rA * 66 + ko + 4],    al3 = Vlu[(rA + 8) * 66 + ko + 4];
#pragma unroll
                for (int tile = 0; tile < 4; tile++) {
                    int n = wc * 32 + tile * 8 + g;
                    uint32_t bh0 = Phu[n * 66 + ko], bh1 = Phu[n * 66 + ko + 4];
                    uint32_t bl0 = Plu[n * 66 + ko], bl1 = Plu[n * 66 + ko + 4];
                    MMA_BF16(acc[tile], ah0, ah1, ah2, ah3, bh0, bh1);
                    MMA_BF16(acc[tile], ah0, ah1, ah2, ah3, bl0, bl1);
                    MMA_BF16(acc[tile], al0, al1, al2, al3, bh0, bh1);
                }
            }
            int trl = wr * 16 + g;
#pragma unroll
            for (int tile = 0; tile < 4; tile++) {
                int c2 = wc * 16 + tile * 4 + tq;
                uint32_t h, l;
                split2(acc[tile][0], acc[tile][1], h, l);
                Thu[trl * 66 + c2] = h; Tlu[trl * 66 + c2] = l;
                split2(acc[tile][2], acc[tile][3], h, l);
                Thu[(trl + 8) * 66 + c2] = h; Tlu[(trl + 8) * 66 + c2] = l;
            }
            __syncthreads();

#pragma unroll
            for (int i = 0; i < 4; i++)
#pragma unroll
                for (int j = 0; j < 4; j++) acc[i][j] = 0.f;
#pragma unroll
            for (int ks = 0; ks < 8; ks++) {
                int ko = ks * 8 + tq;
                uint32_t ah0 = Thu[trl * 66 + ko],       ah1 = Thu[(trl + 8) * 66 + ko];
                uint32_t ah2 = Thu[trl * 66 + ko + 4],   ah3 = Thu[(trl + 8) * 66 + ko + 4];
                uint32_t al0 = Tlu[trl * 66 + ko],       al1 = Tlu[(trl + 8) * 66 + ko];
                uint32_t al2 = Tlu[trl * 66 + ko + 4],   al3 = Tlu[(trl + 8) * 66 + ko + 4];
#pragma unroll
                for (int tile = 0; tile < 4; tile++) {
                    int n = wc * 32 + tile * 8 + g;
                    uint32_t bh0 = Vhu[n * 66 + ko], bh1 = Vhu[n * 66 + ko + 4];
                    uint32_t bl0 = Vlu[n * 66 + ko], bl1 = Vlu[n * 66 + ko + 4];
                    MMA_BF16(acc[tile], ah0, ah1, ah2, ah3, bh0, bh1);
                    MMA_BF16(acc[tile], ah0, ah1, ah2, ah3, bl0, bl1);
                    MMA_BF16(acc[tile], al0, al1, al2, al3, bh0, bh1);
                }
            }
            float mx = 0.f;
            int rowg = r0 + wr * 16 + g;
#pragma unroll
            for (int tile = 0; tile < 4; tile++) {
                int c = wc * 32 + tile * 8 + 2 * tq;
                float2 vm0 = *(const float2*)&Vmg[rowg * 128 + c];
                float2 vm1 = *(const float2*)&Vmg[(rowg + 8) * 128 + c];
                float o0 = 2.0f * vm0.x - acc[tile][0];
                float o1 = 2.0f * vm0.y - acc[tile][1];
                float o2 = 2.0f * vm1.x - acc[tile][2];
                float o3 = 2.0f * vm1.y - acc[tile][3];
                mx = fmaxf(mx, fmaxf(fmaxf(fabsf(o0), fabsf(o1)),
                                     fmaxf(fabsf(o2), fabsf(o3))));
                *(float2*)&Cg[rowg * 128 + c]       = make_float2(o0, o1);
                *(float2*)&Cg[(rowg + 8) * 128 + c] = make_float2(o2, o3);
            }
            red[t] = mx;
            __syncthreads();
            for (int st = 128; st; st >>= 1) {
                if (t < st) red[t] = fmaxf(red[t], red[t + st]);
                __syncthreads();
            }
            if (t == 0) atomicMax(&g_maxc, __float_as_uint(red[0]));
        }
        __syncthreads();
        if (t == 0) {
            __threadfence();
            int gen = *(volatile int*)&g_bar_gen;
            if (atomicAdd(&g_bar_count, 1) == NBLK - 1) {
                g_bar_count = 0;
                if (!g_done) {
                    float m = __uint_as_float(g_maxc);
                    if (m > 10000.0f) g_done = 1;
                    else              g_cur ^= 1;
                    g_maxc = 0u;
                }
                __threadfence();
                *(volatile int*)&g_bar_gen = gen + 1;
            } else {
                while (*(volatile int*)&g_bar_gen == gen) __nanosleep(32);
            }
        }
        __syncthreads();
    }
}

/* ------------------ 6. kv via HMMA v2: coalesced stage -> smem transpose+split -> MMA ----
 * Staging strides padded to multiples of 4 floats (132 / 68) so float4 rows stay 16B-aligned.
 */
__global__ void __launch_bounds__(256) kv_hmma_kernel(const float* __restrict__ V) {
    extern __shared__ unsigned char dsm[];
    uint32_t* Ahu = (uint32_t*)dsm;              /* [128][33] u32 */
    uint32_t* Alu = Ahu + 4224;
    uint32_t* Bhu = Ahu + 8448;                  /* [64][33] */
    uint32_t* Blu = Ahu + 10560;                 /* frags end 50688 B */
    float* k1s = (float*)(dsm + 50688);          /* [64][132] fp32 = 33792 B */
    float* Vs  = (float*)(dsm + 50688 + 33792);  /* [64][68]  fp32 = 17408 B; total 101888 */

    int t = threadIdx.x, lane = t & 31, w = t >> 5;
    int g = lane >> 2, tq = lane & 3;
    int c = blockIdx.x, bh = blockIdx.y;
    const float* k1h = g_k1 + (size_t)bh * 524288;
    const float* Vh  = V + (size_t)bh * 262144;

    float acc[8][4];
#pragma unroll
    for (int i = 0; i < 8; i++)
#pragma unroll
        for (int j = 0; j < 4; j++) acc[i][j] = 0.f;

    for (int sub = 0; sub < 8; sub++) {
        int nb = c * 512 + sub * 64;
        /* phase 1: coalesced float4 loads (row starts 16B-aligned: strides 132/68) */
        for (int i = t; i < 2048; i += 256) {          /* k1 tile 64x128 */
            int n = i >> 5, cq = (i & 31) * 4;
            *(float4*)&k1s[n * 132 + cq] = *(const float4*)&k1h[(size_t)(nb + n) * 128 + cq];
        }
        for (int i = t; i < 1024; i += 256) {          /* V tile 64x64 */
            int n = i >> 4, dq = (i & 15) * 4;
            *(float4*)&Vs[n * 68 + dq] = *(const float4*)&Vh[(size_t)(nb + n) * 64 + dq];
        }
        __syncthreads();
        /* phase 2: smem transpose + split into frag arrays */
        for (int i = t; i < 4096; i += 256) {
            int np = i >> 7, m = i & 127;
            uint32_t h, l;
            split2(k1s[(2 * np) * 132 + m], k1s[(2 * np + 1) * 132 + m], h, l);
            Ahu[m * 33 + np] = h;
            Alu[m * 33 + np] = l;
        }
        for (int i = t; i < 2048; i += 256) {
            int np = i >> 6, d = i & 63;
            uint32_t h, l;
            split2(Vs[(2 * np) * 68 + d], Vs[(2 * np + 1) * 68 + d], h, l);
            Bhu[d * 33 + np] = h;
            Blu[d * 33 + np] = l;
        }
        __syncthreads();
        /* phase 3: MMA */
        int rA = w * 16 + g;
#pragma unroll
        for (int ks = 0; ks < 4; ks++) {
            int ko = ks * 8 + tq;
            uint32_t ah0 = Ahu[rA * 33 + ko],       ah1 = Ahu[(rA + 8) * 33 + ko];
            uint32_t ah2 = Ahu[rA * 33 + ko + 4],   ah3 = Ahu[(rA + 8) * 33 + ko + 4];
            uint32_t al0 = Alu[rA * 33 + ko],       al1 = Alu[(rA + 8) * 33 + ko];
            uint32_t al2 = Alu[rA * 33 + ko + 4],   al3 = Alu[(rA + 8) * 33 + ko + 4];
#pragma unroll
            for (int tile = 0; tile < 8; tile++) {
                int d = tile * 8 + g;
                uint32_t bh0 = Bhu[d * 33 + ko], bh1 = Bhu[d * 33 + ko + 4];
                uint32_t bl0 = Blu[d * 33 + ko], bl1 = Blu[d * 33 + ko + 4];
                MMA_BF16(acc[tile], ah0, ah1, ah2, ah3, bh0, bh1);
                MMA_BF16(acc[tile], ah0, ah1, ah2, ah3, bl0, bl1);
                MMA_BF16(acc[tile], al0, al1, al2, al3, bh0, bh1);
            }
        }
        __syncthreads();
    }

    float* kvp = g_kvp + (size_t)(c * 32 + bh) * 8192;
    int rA = w * 16 + g;
#pragma unroll
    for (int tile = 0; tile < 8; tile++) {
        int d = tile * 8 + 2 * tq;
        *(float2*)&kvp[rA * 64 + d]       = make_float2(acc[tile][0], acc[tile][1]);
        *(float2*)&kvp[(rA + 8) * 64 + d] = make_float2(acc[tile][2], acc[tile][3]);
    }
}

__global__ void kvreduce_kernel() {
    int o = blockIdx.x * 256 + threadIdx.x;
    float s = 0.f;
    for (int c = 0; c < 8; c++) s += g_kvp[(size_t)c * 262144 + o];
    g_kv[o] = s;
}

/* ------------------ 6b. Tm = Vm @ kv ------------------ */
__global__ void mm_tm() {
    const float* A = (*(volatile int*)&g_cur) ? g_VmB : g_VmA;
    int bh = blockIdx.y;
    int tm = blockIdx.x * 64;
    const float* Ah = A + bh * 16384;
    const float* Bh = g_kv + bh * 8192;
    float* Ch = g_Tm + bh * 8192;
    __shared__ float At[16][68], Bt[16][68];
    int t = threadIdx.x, tx = t & 15, ty = t >> 4;
    float acc[4][4];
#pragma unroll
    for (int i = 0; i < 4; i++)
#pragma unroll
        for (int j = 0; j < 4; j++) acc[i][j] = 0.f;
    for (int kc = 0; kc < 128; kc += 16) {
        {
            int r = t >> 2, kq = (t & 3) << 2;
            float4 v = *(const float4*)&Ah[(tm + r) * 128 + kc + kq];
            At[kq + 0][r] = v.x; At[kq + 1][r] = v.y;
            At[kq + 2][r] = v.z; At[kq + 3][r] = v.w;
        }
        {
            int k = t >> 4, cq = (t & 15) << 2;
            if (cq < 64)
                *(float4*)&Bt[k][cq] = *(const float4*)&Bh[(kc + k) * 64 + cq];
        }
        __syncthreads();
#pragma unroll
        for (int k = 0; k < 16; k++) {
            float4 av = *(const float4*)&At[k][ty * 4];
            float4 bv = *(const float4*)&Bt[k][tx * 4];
            float a[4] = {av.x, av.y, av.z, av.w};
            float b[4] = {bv.x, bv.y, bv.z, bv.w};
#pragma unroll
            for (int i = 0; i < 4; i++)
#pragma unroll
                for (int j = 0; j < 4; j++) acc[i][j] += a[i] * b[j];
        }
        __syncthreads();
    }
#pragma unroll
    for (int i = 0; i < 4; i++) {
        int row = tm + ty * 4 + i;
        *(float4*)&Ch[row * 64 + tx * 4] =
            make_float4(acc[i][0], acc[i][1], acc[i][2], acc[i][3]);
    }
}

/* ------------------ 7. final via HMMA: X = k1 @ Tm + depthwise conv(V) ------------------ */
__global__ void __launch_bounds__(256) final_hmma_kernel(const float* __restrict__ V,
                                                         const float* __restrict__ cw,
                                                         float* __restrict__ out) {
    extern __shared__ unsigned char dsm[];
    uint32_t* K1hu  = (uint32_t*)dsm;        /* [128][66] u32 */
    uint32_t* K1lu  = K1hu + 8448;
    uint32_t* TmThu = K1hu + 16896;          /* [64][66] u32 : TmT[d][m] */
    uint32_t* TmTlu = K1hu + 21120;          /* total 25344 u32 = 101376 B */

    int t = threadIdx.x, lane = t & 31, w = t >> 5;
    int g = lane >> 2, tq = lane & 3;
    int bh = blockIdx.y, n0 = blockIdx.x * 128;
    const float* k1g = g_k1 + (size_t)bh * 524288 + (size_t)n0 * 128;
    const float* Tmg = g_Tm + bh * 8192;

    split_tile_128(k1g, K1hu, K1lu, t);
    for (int i = t; i < 4096; i += 256) {
        int d = i >> 6, mp = i & 63;
        float x = Tmg[(2 * mp) * 64 + d];
        float y = Tmg[(2 * mp + 1) * 64 + d];
        uint32_t h, l;
        split2(x, y, h, l);
        TmThu[d * 66 + mp] = h;
        TmTlu[d * 66 + mp] = l;
    }
    __syncthreads();

    float acc[8][4];
#pragma unroll
    for (int i = 0; i < 8; i++)
#pragma unroll
        for (int j = 0; j < 4; j++) acc[i][j] = 0.f;
    int rA = w * 16 + g;
#pragma unroll
    for (int ks = 0; ks < 8; ks++) {
        int ko = ks * 8 + tq;
        uint32_t ah0 = K1hu[rA * 66 + ko],       ah1 = K1hu[(rA + 8) * 66 + ko];
        uint32_t ah2 = K1hu[rA * 66 + ko + 4],   ah3 = K1hu[(rA + 8) * 66 + ko + 4];
        uint32_t al0 = K1lu[rA * 66 + ko],       al1 = K1lu[(rA + 8) * 66 + ko];
        uint32_t al2 = K1lu[rA * 66 + ko + 4],   al3 = K1lu[(rA + 8) * 66 + ko + 4];
#pragma unroll
        for (int tile = 0; tile < 8; tile++) {
            int n = tile * 8 + g;
            uint32_t bh0 = TmThu[n * 66 + ko], bh1 = TmThu[n * 66 + ko + 4];
            uint32_t bl0 = TmTlu[n * 66 + ko], bl1 = TmTlu[n * 66 + ko + 4];
            MMA_BF16(acc[tile], ah0, ah1, ah2, ah3, bh0, bh1);
            MMA_BF16(acc[tile], ah0, ah1, ah2, ah3, bl0, bl1);
            MMA_BF16(acc[tile], al0, al1, al2, al3, bh0, bh1);
        }
    }

    int h = bh & 15;
    float w0 = cw[h * 3], w1 = cw[h * 3 + 1], w2 = cw[h * 3 + 2];
    const float* Vh = V + (size_t)bh * 262144;
    float* oh = out + (size_t)bh * 262144;
#pragma unroll
    for (int tile = 0; tile < 8; tile++) {
        int d = tile * 8 + 2 * tq;
#pragma unroll
        for (int rr = 0; rr < 2; rr++) {
            int n = n0 + w * 16 + g + rr * 8;
            float a0 = acc[tile][rr * 2], a1 = acc[tile][rr * 2 + 1];
            float2 vc = *(const float2*)&Vh[(size_t)n * 64 + d];
            float2 vp = (n > 0)    ? *(const float2*)&Vh[(size_t)(n - 1) * 64 + d] : make_float2(0.f, 0.f);
            float2 vn = (n < 4095) ? *(const float2*)&Vh[(size_t)(n + 1) * 64 + d] : make_float2(0.f, 0.f);
            float2 o;
            o.x = a0 + w0 * vp.x + w1 * vc.x + w2 * vn.x;
            o.y = a1 + w0 * vp.y + w1 * vc.y + w2 * vn.y;
            *(float2*)&oh[(size_t)n * 64 + d] = o;
        }
    }
}

/* ------------------ launch ------------------ */
extern "C" void kernel_launch(void* const* d_in, const int* in_sizes, int n_in,
                              void* d_out, int out_size) {
    (void)in_sizes; (void)n_in; (void)out_size;
    const float* Q     = (const float*)d_in[0];
    const float* V     = (const float*)d_in[1];
    const float* Wland = (const float*)d_in[2];
    const float* gamma = (const float*)d_in[3];
    const float* beta  = (const float*)d_in[4];
    const float* convw = (const float*)d_in[5];
    float* out = (float*)d_out;

    cudaFuncSetAttribute(k1_hmma_kernel,
                         cudaFuncAttributeMaxDynamicSharedMemorySize, 52224);
    cudaFuncSetAttribute(newton_persistent,
                         cudaFuncAttributeMaxDynamicSharedMemorySize, 152064);
    cudaFuncSetAttribute(final_hmma_kernel,
                         cudaFuncAttributeMaxDynamicSharedMemorySize, 101376);
    cudaFuncSetAttribute(prep_kernel,
                         cudaFuncAttributeMaxDynamicSharedMemorySize, 66048);
    cudaFuncSetAttribute(kv_hmma_kernel,
                         cudaFuncAttributeMaxDynamicSharedMemorySize, 101888);

    wtrans_kernel<<<512, 256>>>(Wland);
    landmark_kernel<<<dim3(4, BH), 256>>>(Q, gamma, beta);
    k2_kernel<<<BH, 256>>>();
    k1_hmma_kernel<<<dim3(32, BH), 256, 51712>>>(Q);
    prep_kernel<<<BH, 128, 66048>>>();
    alpha_kernel<<<1, 256>>>();
    vminit_kernel<<<512, 256>>>();
    newton_persistent<<<NBLK, 256, 152064>>>();
    kv_hmma_kernel<<<dim3(8, BH), 256, 101888>>>(V);
    kvreduce_kernel<<<1024, 256>>>();
    mm_tm<<<dim3(2, BH), 256>>>();
    final_hmma_kernel<<<dim3(32, BH), 256, 101376>>>(V, convw, out);
}

// round 16
// speedup vs baseline: 1.1115x; 1.0308x over previous
#include <cuda_runtime.h>
#include <cuda_bf16.h>
#include <math.h>
#include <stdint.h>

#define BH     32
#define NSEQ   4096
#define DDIM   64
#define MLAND  128
#define NBLK   128
#define SCALEF 0.3535533905932738f   /* 64^-0.25 */

/* ------------------ scratch: __device__ globals (no allocs) ------------------ */
__device__ __align__(16) float g_Wt[2048 * 64];
__device__ __align__(16) float g_QL[BH * MLAND * DDIM];
__device__ __align__(16) float g_ln[BH * MLAND];
__device__ __align__(16) float g_P [BH * MLAND * MLAND];
__device__ __align__(16) float g_VmA[BH * MLAND * MLAND];
__device__ __align__(16) float g_VmB[BH * MLAND * MLAND];
__device__ __align__(16) float g_cs[BH * MLAND];
__device__ __align__(16) float g_dg[BH * MLAND];
__device__ __align__(16) float g_kv [BH * MLAND * DDIM];
__device__ __align__(16) float g_kvp[16 * BH * MLAND * DDIM];
__device__ __align__(16) float g_Tm[BH * MLAND * DDIM];
__device__ __align__(16) float g_k1[(size_t)BH * NSEQ * MLAND]; /* 64 MB */
__device__ float    g_alpha;
__device__ unsigned g_maxrs;
__device__ unsigned g_maxc;
__device__ int      g_done;
__device__ int      g_cur;
__device__ int      g_bar_count;
__device__ int      g_bar_gen;

__device__ __forceinline__ uint32_t pack_bf2(__nv_bfloat16 a, __nv_bfloat16 b) {
    return (uint32_t)__bfloat16_as_ushort(a) | ((uint32_t)__bfloat16_as_ushort(b) << 16);
}
__device__ __forceinline__ void split2(float x, float y, uint32_t& hi, uint32_t& lo) {
    __nv_bfloat16 hx = __float2bfloat16(x), hy = __float2bfloat16(y);
    hi = pack_bf2(hx, hy);
    lo = pack_bf2(__float2bfloat16(x - __bfloat162float(hx)),
                  __float2bfloat16(y - __bfloat162float(hy)));
}
#define MMA_BF16(c, a0, a1, a2, a3, b0, b1)                                  \
    asm volatile("mma.sync.aligned.m16n8k16.row.col.f32.bf16.bf16.f32 "      \
        "{%0,%1,%2,%3}, {%4,%5,%6,%7}, {%8,%9}, {%0,%1,%2,%3};"              \
        : "+f"((c)[0]), "+f"((c)[1]), "+f"((c)[2]), "+f"((c)[3])             \
        : "r"(a0), "r"(a1), "r"(a2), "r"(a3), "r"(b0), "r"(b1))

/* split 128x128 fp32 (global, row stride 128) -> hi/lo u32 smem (row stride 66) */
__device__ __forceinline__ void split_tile_128(const float* __restrict__ g,
                                               uint32_t* hi, uint32_t* lo, int t) {
    for (int i = t; i < 8192; i += 256) {
        float2 v = ((const float2*)g)[i];
        uint32_t h, l;
        split2(v.x, v.y, h, l);
        int row = i >> 6, cp = i & 63;
        hi[row * 66 + cp] = h;
        lo[row * 66 + cp] = l;
    }
}

/* ------------------ 0. weight relayout (+ reset g_maxrs) ------------------ */
__global__ void wtrans_kernel(const float* __restrict__ W) {
    int idx = blockIdx.x * 256 + threadIdx.x;
    if (idx == 0) g_maxrs = 0u;
    int o = idx >> 11, i = (idx >> 5) & 63, k = idx & 31;
    g_Wt[(k * 64 + i) * 64 + o] = W[idx];
}

/* ------------------ 1. landmarks: GEMM + LayerNorm + exact GELU ------------------ */
__global__ void landmark_kernel(const float* __restrict__ Q,
                                const float* __restrict__ gamma,
                                const float* __restrict__ beta) {
    __shared__ float As[32][68];
    __shared__ float Ws[64][68];
    __shared__ float S[32][65];
    int bh = blockIdx.y, mb = blockIdx.x;
    int t = threadIdx.x;
    int tx = t & 63, ty = t >> 6;
    const float* qbase = Q + (size_t)bh * 262144 + (size_t)mb * 65536;
    float acc[8] = {0.f,0.f,0.f,0.f,0.f,0.f,0.f,0.f};
    for (int kc = 0; kc < 2048; kc += 64) {
        for (int idx = t; idx < 2048; idx += 256) {
            int r = idx >> 6, k = idx & 63;
            As[r][k] = qbase[r * 2048 + kc + k] * SCALEF;
        }
        for (int idx = t; idx < 4096; idx += 256) {
            int o = idx & 63, k = idx >> 6;
            Ws[o][k] = g_Wt[(kc + k) * 64 + o];
        }
        __syncthreads();
#pragma unroll
        for (int k4 = 0; k4 < 64; k4 += 4) {
            float4 w = *(const float4*)&Ws[tx][k4];
#pragma unroll
            for (int j = 0; j < 8; j++) {
                float4 a = *(const float4*)&As[ty * 8 + j][k4];
                acc[j] += a.x * w.x + a.y * w.y + a.z * w.z + a.w * w.w;
            }
        }
        __syncthreads();
    }
#pragma unroll
    for (int j = 0; j < 8; j++) S[ty * 8 + j][tx] = acc[j];
    __syncthreads();
    int warp = t >> 5, lane = t & 31;
    for (int rr = 0; rr < 4; rr++) {
        int row = warp * 4 + rr;
        float x0 = S[row][lane], x1 = S[row][lane + 32];
        float s = x0 + x1;
#pragma unroll
        for (int off = 16; off; off >>= 1) s += __shfl_xor_sync(0xffffffffu, s, off);
        float mu = s * (1.0f / 64.0f);
        float d0 = x0 - mu, d1 = x1 - mu;
        float v = d0 * d0 + d1 * d1;
#pragma unroll
        for (int off = 16; off; off >>= 1) v += __shfl_xor_sync(0xffffffffu, v, off);
        float rstd = rsqrtf(v * (1.0f / 64.0f) + 1e-5f);
        int mg = bh * 128 + mb * 32 + row;
#pragma unroll
        for (int cc = 0; cc < 2; cc++) {
            int c = lane + cc * 32;
            float x = cc ? x1 : x0;
            float y = (x - mu) * rstd * gamma[c] + beta[c];
            float g = 0.5f * y * (1.0f + erff(y * 0.70710678118654752f));
            g_QL[mg * 64 + c] = g;
        }
    }
}

/* ------------------ 2. k2 + prep fused: P, rs, dg, cs (P symmetric) ------------------ */
__global__ void __launch_bounds__(256) k2_prep_kernel() {
    extern __shared__ float Psh[];               /* [128][129] fp32 = 66048 B */
    __shared__ float QLt[64][132];
    __shared__ float lnorm[128];
    __shared__ float rss[128];
    __shared__ float red[128];
    int bh = blockIdx.x, t = threadIdx.x;
    const float* ql = g_QL + bh * 8192;
    for (int idx = t; idx < 8192; idx += 256) {
        int m = idx >> 6, k = idx & 63;
        QLt[k][m] = ql[idx];
    }
    __syncthreads();
    if (t < 128) {
        float s = 0.f;
        for (int k = 0; k < 64; k++) { float v = QLt[k][t]; s += v * v; }
        lnorm[t] = s;
        g_ln[bh * 128 + t] = s;
    }
    __syncthreads();
    int tx = t & 15, ty = t >> 4;
    float acc[8][8];
#pragma unroll
    for (int i = 0; i < 8; i++)
#pragma unroll
        for (int j = 0; j < 8; j++) acc[i][j] = 0.f;
#pragma unroll 4
    for (int k = 0; k < 64; k++) {
        float4 a0 = *(const float4*)&QLt[k][ty * 8];
        float4 a1 = *(const float4*)&QLt[k][ty * 8 + 4];
        float4 b0 = *(const float4*)&QLt[k][tx * 8];
        float4 b1 = *(const float4*)&QLt[k][tx * 8 + 4];
        float a[8] = {a0.x,a0.y,a0.z,a0.w,a1.x,a1.y,a1.z,a1.w};
        float b[8] = {b0.x,b0.y,b0.z,b0.w,b1.x,b1.y,b1.z,b1.w};
#pragma unroll
        for (int i = 0; i < 8; i++)
#pragma unroll
            for (int j = 0; j < 8; j++) acc[i][j] += a[i] * b[j];
    }
    float* Ph = g_P + bh * 16384;
#pragma unroll
    for (int i = 0; i < 8; i++) {
        int m = ty * 8 + i;
        float o[8];
#pragma unroll
        for (int j = 0; j < 8; j++) {
            float d = lnorm[m] + lnorm[tx * 8 + j] - 2.0f * acc[i][j];
            d = fmaxf(d, 0.0f);
            o[j] = expf(-0.5f * d);
            Psh[m * 129 + tx * 8 + j] = o[j];
        }
        *(float4*)&Ph[m * 128 + tx * 8]     = make_float4(o[0], o[1], o[2], o[3]);
        *(float4*)&Ph[m * 128 + tx * 8 + 4] = make_float4(o[4], o[5], o[6], o[7]);
    }
    __syncthreads();
    if (t < 128) {
        float rs = 0.f, dg = 0.f;
        for (int k = 0; k < 128; k++) {
            float v = Psh[t * 129 + k];
            rs += v; dg += v * v;
        }
        rss[t] = rs;
        g_dg[bh * 128 + t] = dg;
        red[t] = rs;
    }
    __syncthreads();
    for (int st = 64; st; st >>= 1) {
        if (t < st) red[t] = fmaxf(red[t], red[t + st]);
        __syncthreads();
    }
    if (t == 0) atomicMax(&g_maxrs, __float_as_uint(red[0]));
    if (t < 128) {
        float cs = 0.f;
        for (int k = 0; k < 128; k++) cs += rss[k] * Psh[k * 129 + t];
        g_cs[bh * 128 + t] = cs;
    }
}

/* ------------------ 3. k1 via HMMA v3: A pre-split into u32 frag arrays ------------------ */
__global__ void __launch_bounds__(256) k1_hmma_kernel(const float* __restrict__ Q) {
    extern __shared__ unsigned char dsm[];
    uint32_t* Ahi = (uint32_t*)dsm;                  /* [128][33] u32 = 16896 B */
    uint32_t* Alo = Ahi + 4224;                      /* 16896 B; end 33792 */
    float* s_qn = (float*)(dsm + 33792);
    float* s_ln = s_qn + 128;
    __nv_bfloat16* Bh = (__nv_bfloat16*)(dsm + 34816);   /* [64][66] */
    __nv_bfloat16* Bl = Bh + 64 * 66;                    /* total 51712 */

    int t = threadIdx.x, lane = t & 31, w = t >> 5;
    int bh = blockIdx.y, n0 = blockIdx.x * 128;

    {
        int row = t >> 1, kh = (t & 1) * 32;
        int npb = (t & 1) * 16;
        const float* qrow = Q + (size_t)bh * 262144 + (size_t)(n0 + row) * 64 + kh;
        float part = 0.f;
#pragma unroll
        for (int i = 0; i < 8; i++) {
            float4 v = *(const float4*)&qrow[i * 4];
            float x0 = v.x * SCALEF, x1 = v.y * SCALEF;
            float x2 = v.z * SCALEF, x3 = v.w * SCALEF;
            part += x0 * x0 + x1 * x1 + x2 * x2 + x3 * x3;
            uint32_t h0, l0, h1, l1;
            split2(x0, x1, h0, l0);
            split2(x2, x3, h1, l1);
            Ahi[row * 33 + npb + i * 2]     = h0;
            Ahi[row * 33 + npb + i * 2 + 1] = h1;
            Alo[row * 33 + npb + i * 2]     = l0;
            Alo[row * 33 + npb + i * 2 + 1] = l1;
        }
        part += __shfl_xor_sync(0xffffffffu, part, 1);
        if ((t & 1) == 0) s_qn[row] = part;
        if (t < 128) s_ln[t] = g_ln[bh * 128 + t];
    }

    float* k1h = g_k1 + (size_t)bh * 524288 + (size_t)n0 * 128;
    int r0 = w * 16;
    int row0 = r0 + (lane >> 2);
    int tq = lane & 3;
    int kq = tq * 2;

    for (int half = 0; half < 2; half++) {
        __syncthreads();
        {
            int mrow = t >> 2, ks = (t & 3) * 16;
            const float* lrow = g_QL + bh * 8192 + (size_t)(half * 64 + mrow) * 64 + ks;
            uint32_t* bhp = (uint32_t*)(Bh + mrow * 66 + ks);
            uint32_t* blp = (uint32_t*)(Bl + mrow * 66 + ks);
#pragma unroll
            for (int i = 0; i < 4; i++) {
                float4 v = *(const float4*)&lrow[i * 4];
                uint32_t h0, l0, h1, l1;
                split2(v.x, v.y, h0, l0);
                split2(v.z, v.w, h1, l1);
                bhp[i * 2] = h0; bhp[i * 2 + 1] = h1;
                blp[i * 2] = l0; blp[i * 2 + 1] = l1;
            }
        }
        __syncthreads();

        float acc[8][4];
#pragma unroll
        for (int i = 0; i < 8; i++)
#pragma unroll
            for (int j = 0; j < 4; j++) acc[i][j] = 0.f;

#pragma unroll
        for (int ks = 0; ks < 4; ks++) {
            int ko = ks * 8 + tq;
            uint32_t ah0 = Ahi[row0 * 33 + ko],       ah1 = Ahi[(row0 + 8) * 33 + ko];
            uint32_t ah2 = Ahi[row0 * 33 + ko + 4],   ah3 = Ahi[(row0 + 8) * 33 + ko + 4];
            uint32_t al0 = Alo[row0 * 33 + ko],       al1 = Alo[(row0 + 8) * 33 + ko];
            uint32_t al2 = Alo[row0 * 33 + ko + 4],   al3 = Alo[(row0 + 8) * 33 + ko + 4];
            int k0 = ks * 16 + kq;
#pragma unroll
            for (int tile = 0; tile < 8; tile++) {
                int n = tile * 8 + (lane >> 2);
                const uint32_t* bhp = (const uint32_t*)(Bh + n * 66 + k0);
                const uint32_t* blp = (const uint32_t*)(Bl + n * 66 + k0);
                uint32_t bh0 = bhp[0], bh1 = bhp[4];
                uint32_t bl0 = blp[0], bl1 = blp[4];
                MMA_BF16(acc[tile], ah0, ah1, ah2, ah3, bh0, bh1);
                MMA_BF16(acc[tile], ah0, ah1, ah2, ah3, bl0, bl1);
                MMA_BF16(acc[tile], al0, al1, al2, al3, bh0, bh1);
            }
        }

        float qn0 = s_qn[row0], qn1 = s_qn[row0 + 8];
#pragma unroll
        for (int tile = 0; tile < 8; tile++) {
            int col = half * 64 + tile * 8 + kq;
            float l0 = s_ln[col], l1 = s_ln[col + 1];
            float d00 = fmaxf(qn0 + l0 - 2.0f * acc[tile][0], 0.f);
            float d01 = fmaxf(qn0 + l1 - 2.0f * acc[tile][1], 0.f);
            float d10 = fmaxf(qn1 + l0 - 2.0f * acc[tile][2], 0.f);
            float d11 = fmaxf(qn1 + l1 - 2.0f * acc[tile][3], 0.f);
            *(float2*)&k1h[(size_t)row0 * 128 + col] =
                make_float2(__expf(-0.5f * d00), __expf(-0.5f * d01));
            *(float2*)&k1h[(size_t)(row0 + 8) * 128 + col] =
                make_float2(__expf(-0.5f * d10), __expf(-0.5f * d11));
        }
    }
}

/* ------------------ 4c. alpha init + 10 halvings (one block) ------------------ */
__global__ void alpha_kernel() {
    __shared__ float red[256];
    __shared__ float sh_alpha;
    int t = threadIdx.x;
    if (t == 0) {
        float mr = __uint_as_float(g_maxrs);
        sh_alpha = 2.0f / (mr * mr);
    }
    __syncthreads();
    for (int it = 0; it < 10; it++) {
        float a = sh_alpha;
        float mx = 0.f;
        for (int idx = t; idx < 4096; idx += 256) {
            float cs = g_cs[idx], dg = g_dg[idx];
            float v = a * (cs - dg) + fabsf(1.0f - a * dg);
            mx = fmaxf(mx, v);
        }
        red[t] = mx;
        __syncthreads();
        for (int st = 128; st; st >>= 1) {
            if (t < st) red[t] = fmaxf(red[t], red[t + st]);
            __syncthreads();
        }
        if (t == 0 && red[0] > 1.01f) sh_alpha = a * 0.5f;
        __syncthreads();
    }
    if (t == 0) { g_alpha = sh_alpha; g_done = 0; g_maxc = 0u; g_cur = 0; }
}

/* ------------------ 4d. VmA = alpha * P ------------------ */
__global__ void vminit_kernel() {
    int i = blockIdx.x * 256 + threadIdx.x;
    float a = g_alpha;
    float4 p = ((const float4*)g_P)[i];
    ((float4*)g_VmA)[i] = make_float4(a * p.x, a * p.y, a * p.z, a * p.w);
}

/* ------------------ 5. persistent Newton via HMMA; decide fused into barrier ------------------ */
__global__ void __launch_bounds__(256, 1) newton_persistent() {
    extern __shared__ unsigned char dsm[];
    uint32_t* Phu = (uint32_t*)dsm;          /* [128][66] u32 */
    uint32_t* Plu = Phu + 8448;
    uint32_t* Vhu = Phu + 16896;
    uint32_t* Vlu = Phu + 25344;
    uint32_t* Thu = Phu + 33792;             /* [32][66] */
    uint32_t* Tlu = Phu + 35904;             /* total 38016 u32 = 152064 B */
    __shared__ float red[256];

    int t = threadIdx.x, lane = t & 31, w = t >> 5;
    int wr = w >> 2, wc = w & 3;
    int g = lane >> 2, tq = lane & 3;
    int bh = blockIdx.x >> 2;
    int r0 = (blockIdx.x & 3) * 32;
    const float* Pg = g_P + bh * 16384;

    split_tile_128(Pg, Phu, Plu, t);

    for (int it = 0; it < 20; it++) {
        if (!(*(volatile int*)&g_done)) {
            int cur = *(volatile int*)&g_cur;
            const float* Vmg = (cur ? g_VmB : g_VmA) + bh * 16384;
            float*       Cg  = (cur ? g_VmA : g_VmB) + bh * 16384;
            __syncthreads();
            split_tile_128(Vmg, Vhu, Vlu, t);
            __syncthreads();

            float acc[4][4];
#pragma unroll
            for (int i = 0; i < 4; i++)
#pragma unroll
                for (int j = 0; j < 4; j++) acc[i][j] = 0.f;
            int rA = r0 + wr * 16 + g;
#pragma unroll
            for (int ks = 0; ks < 8; ks++) {
                int ko = ks * 8 + tq;
                uint32_t ah0 = Vhu[rA * 66 + ko],        ah1 = Vhu[(rA + 8) * 66 + ko];
                uint32_t ah2 = Vhu[rA * 66 + ko + 4],    ah3 = Vhu[(rA + 8) * 66 + ko + 4];
                uint32_t al0 = Vlu[rA * 66 + ko],        al1 = Vlu[(rA + 8) * 66 + ko];
                uint32_t al2 = Vlu[rA * 66 + ko + 4],    al3 = Vlu[(rA + 8) * 66 + ko + 4];
#pragma unroll
                for (int tile = 0; tile < 4; tile++) {
                    int n = wc * 32 + tile * 8 + g;
                    uint32_t bh0 = Phu[n * 66 + ko], bh1 = Phu[n * 66 + ko + 4];
                    uint32_t bl0 = Plu[n * 66 + ko], bl1 = Plu[n * 66 + ko + 4];
                    MMA_BF16(acc[tile], ah0, ah1, ah2, ah3, bh0, bh1);
                    MMA_BF16(acc[tile], ah0, ah1, ah2, ah3, bl0, bl1);
                    MMA_BF16(acc[tile], al0, al1, al2, al3, bh0, bh1);
                }
            }
            int trl = wr * 16 + g;
#pragma unroll
            for (int tile = 0; tile < 4; tile++) {
                int c2 = wc * 16 + tile * 4 + tq;
                uint32_t h, l;
                split2(acc[tile][0], acc[tile][1], h, l);
                Thu[trl * 66 + c2] = h; Tlu[trl * 66 + c2] = l;
                split2(acc[tile][2], acc[tile][3], h, l);
                Thu[(trl + 8) * 66 + c2] = h; Tlu[(trl + 8) * 66 + c2] = l;
            }
            __syncthreads();

#pragma unroll
            for (int i = 0; i < 4; i++)
#pragma unroll
                for (int j = 0; j < 4; j++) acc[i][j] = 0.f;
#pragma unroll
            for (int ks = 0; ks < 8; ks++) {
                int ko = ks * 8 + tq;
                uint32_t ah0 = Thu[trl * 66 + ko],       ah1 = Thu[(trl + 8) * 66 + ko];
                uint32_t ah2 = Thu[trl * 66 + ko + 4],   ah3 = Thu[(trl + 8) * 66 + ko + 4];
                uint32_t al0 = Tlu[trl * 66 + ko],       al1 = Tlu[(trl + 8) * 66 + ko];
                uint32_t al2 = Tlu[trl * 66 + ko + 4],   al3 = Tlu[(trl + 8) * 66 + ko + 4];
#pragma unroll
                for (int tile = 0; tile < 4; tile++) {
                    int n = wc * 32 + tile * 8 + g;
                    uint32_t bh0 = Vhu[n * 66 + ko], bh1 = Vhu[n * 66 + ko + 4];
                    uint32_t bl0 = Vlu[n * 66 + ko], bl1 = Vlu[n * 66 + ko + 4];
                    MMA_BF16(acc[tile], ah0, ah1, ah2, ah3, bh0, bh1);
                    MMA_BF16(acc[tile], ah0, ah1, ah2, ah3, bl0, bl1);
                    MMA_BF16(acc[tile], al0, al1, al2, al3, bh0, bh1);
                }
            }
            float mx = 0.f;
            int rowg = r0 + wr * 16 + g;
#pragma unroll
            for (int tile = 0; tile < 4; tile++) {
                int c = wc * 32 + tile * 8 + 2 * tq;
                float2 vm0 = *(const float2*)&Vmg[rowg * 128 + c];
                float2 vm1 = *(const float2*)&Vmg[(rowg + 8) * 128 + c];
                float o0 = 2.0f * vm0.x - acc[tile][0];
                float o1 = 2.0f * vm0.y - acc[tile][1];
                float o2 = 2.0f * vm1.x - acc[tile][2];
                float o3 = 2.0f * vm1.y - acc[tile][3];
                mx = fmaxf(mx, fmaxf(fmaxf(fabsf(o0), fabsf(o1)),
                                     fmaxf(fabsf(o2), fabsf(o3))));
                *(float2*)&Cg[rowg * 128 + c]       = make_float2(o0, o1);
                *(float2*)&Cg[(rowg + 8) * 128 + c] = make_float2(o2, o3);
            }
            red[t] = mx;
            __syncthreads();
            for (int st = 128; st; st >>= 1) {
                if (t < st) red[t] = fmaxf(red[t], red[t + st]);
                __syncthreads();
            }
            if (t == 0) atomicMax(&g_maxc, __float_as_uint(red[0]));
        }
        __syncthreads();
        if (t == 0) {
            __threadfence();
            int gen = *(volatile int*)&g_bar_gen;
            if (atomicAdd(&g_bar_count, 1) == NBLK - 1) {
                g_bar_count = 0;
                if (!g_done) {
                    float m = __uint_as_float(g_maxc);
                    if (m > 10000.0f) g_done = 1;
                    else              g_cur ^= 1;
                    g_maxc = 0u;
                }
                __threadfence();
                *(volatile int*)&g_bar_gen = gen + 1;
            } else {
                while (*(volatile int*)&g_bar_gen == gen) __nanosleep(32);
            }
        }
        __syncthreads();
    }
}

/* ------------------ 6. kv via HMMA: coalesced stage -> smem transpose+split -> MMA ---- */
__global__ void __launch_bounds__(256) kv_hmma_kernel(const float* __restrict__ V) {
    extern __shared__ unsigned char dsm[];
    uint32_t* Ahu = (uint32_t*)dsm;              /* [128][33] u32 */
    uint32_t* Alu = Ahu + 4224;
    uint32_t* Bhu = Ahu + 8448;                  /* [64][33] */
    uint32_t* Blu = Ahu + 10560;                 /* frags end 50688 B */
    float* k1s = (float*)(dsm + 50688);          /* [64][132] fp32 = 33792 B */
    float* Vs  = (float*)(dsm + 50688 + 33792);  /* [64][68]  fp32 = 17408 B; total 101888 */

    int t = threadIdx.x, lane = t & 31, w = t >> 5;
    int g = lane >> 2, tq = lane & 3;
    int c = blockIdx.x, bh = blockIdx.y;
    const float* k1h = g_k1 + (size_t)bh * 524288;
    const float* Vh  = V + (size_t)bh * 262144;

    float acc[8][4];
#pragma unroll
    for (int i = 0; i < 8; i++)
#pragma unroll
        for (int j = 0; j < 4; j++) acc[i][j] = 0.f;

    for (int sub = 0; sub < 8; sub++) {
        int nb = c * 512 + sub * 64;
        for (int i = t; i < 2048; i += 256) {
            int n = i >> 5, cq = (i & 31) * 4;
            *(float4*)&k1s[n * 132 + cq] = *(const float4*)&k1h[(size_t)(nb + n) * 128 + cq];
        }
        for (int i = t; i < 1024; i += 256) {
            int n = i >> 4, dq = (i & 15) * 4;
            *(float4*)&Vs[n * 68 + dq] = *(const float4*)&Vh[(size_t)(nb + n) * 64 + dq];
        }
        __syncthreads();
        for (int i = t; i < 4096; i += 256) {
            int np = i >> 7, m = i & 127;
            uint32_t h, l;
            split2(k1s[(2 * np) * 132 + m], k1s[(2 * np + 1) * 132 + m], h, l);
            Ahu[m * 33 + np] = h;
            Alu[m * 33 + np] = l;
        }
        for (int i = t; i < 2048; i += 256) {
            int np = i >> 6, d = i & 63;
            uint32_t h, l;
            split2(Vs[(2 * np) * 68 + d], Vs[(2 * np + 1) * 68 + d], h, l);
            Bhu[d * 33 + np] = h;
            Blu[d * 33 + np] = l;
        }
        __syncthreads();
        int rA = w * 16 + g;
#pragma unroll
        for (int ks = 0; ks < 4; ks++) {
            int ko = ks * 8 + tq;
            uint32_t ah0 = Ahu[rA * 33 + ko],       ah1 = Ahu[(rA + 8) * 33 + ko];
            uint32_t ah2 = Ahu[rA * 33 + ko + 4],   ah3 = Ahu[(rA + 8) * 33 + ko + 4];
            uint32_t al0 = Alu[rA * 33 + ko],       al1 = Alu[(rA + 8) * 33 + ko];
            uint32_t al2 = Alu[rA * 33 + ko + 4],   al3 = Alu[(rA + 8) * 33 + ko + 4];
#pragma unroll
            for (int tile = 0; tile < 8; tile++) {
                int d = tile * 8 + g;
                uint32_t bh0 = Bhu[d * 33 + ko], bh1 = Bhu[d * 33 + ko + 4];
                uint32_t bl0 = Blu[d * 33 + ko], bl1 = Blu[d * 33 + ko + 4];
                MMA_BF16(acc[tile], ah0, ah1, ah2, ah3, bh0, bh1);
                MMA_BF16(acc[tile], ah0, ah1, ah2, ah3, bl0, bl1);
                MMA_BF16(acc[tile], al0, al1, al2, al3, bh0, bh1);
            }
        }
        __syncthreads();
    }

    float* kvp = g_kvp + (size_t)(c * 32 + bh) * 8192;
    int rA = w * 16 + g;
#pragma unroll
    for (int tile = 0; tile < 8; tile++) {
        int d = tile * 8 + 2 * tq;
        *(float2*)&kvp[rA * 64 + d]       = make_float2(acc[tile][0], acc[tile][1]);
        *(float2*)&kvp[(rA + 8) * 64 + d] = make_float2(acc[tile][2], acc[tile][3]);
    }
}

/* ------------------ 6b. Tm = Vm @ kv; kvp partials reduced inline ------------------ */
__global__ void mm_tm() {
    const float* A = (*(volatile int*)&g_cur) ? g_VmB : g_VmA;
    int bh = blockIdx.y;
    int tm = blockIdx.x * 64;
    const float* Ah = A + bh * 16384;
    float* Ch = g_Tm + bh * 8192;
    __shared__ float At[16][68], Bt[16][68];
    int t = threadIdx.x, tx = t & 15, ty = t >> 4;
    float acc[4][4];
#pragma unroll
    for (int i = 0; i < 4; i++)
#pragma unroll
        for (int j = 0; j < 4; j++) acc[i][j] = 0.f;
    for (int kc = 0; kc < 128; kc += 16) {
        {
            int r = t >> 2, kq = (t & 3) << 2;
            float4 v = *(const float4*)&Ah[(tm + r) * 128 + kc + kq];
            At[kq + 0][r] = v.x; At[kq + 1][r] = v.y;
            At[kq + 2][r] = v.z; At[kq + 3][r] = v.w;
        }
        {
            int k = t >> 4, cq = (t & 15) << 2;
            if (cq < 64) {
                size_t off = (size_t)bh * 8192 + (size_t)(kc + k) * 64 + cq;
                float4 s = make_float4(0.f, 0.f, 0.f, 0.f);
#pragma unroll
                for (int cc = 0; cc < 8; cc++) {
                    float4 v = *(const float4*)&g_kvp[(size_t)cc * 262144 + off];
                    s.x += v.x; s.y += v.y; s.z += v.z; s.w += v.w;
                }
                *(float4*)&Bt[k][cq] = s;
            }
        }
        __syncthreads();
#pragma unroll
        for (int k = 0; k < 16; k++) {
            float4 av = *(const float4*)&At[k][ty * 4];
            float4 bv = *(const float4*)&Bt[k][tx * 4];
            float a[4] = {av.x, av.y, av.z, av.w};
            float b[4] = {bv.x, bv.y, bv.z, bv.w};
#pragma unroll
            for (int i = 0; i < 4; i++)
#pragma unroll
                for (int j = 0; j < 4; j++) acc[i][j] += a[i] * b[j];
        }
        __syncthreads();
    }
#pragma unroll
    for (int i = 0; i < 4; i++) {
        int row = tm + ty * 4 + i;
        *(float4*)&Ch[row * 64 + tx * 4] =
            make_float4(acc[i][0], acc[i][1], acc[i][2], acc[i][3]);
    }
}

/* ------------------ 7. final via HMMA: X = k1 @ Tm + depthwise conv(V) ------------------ */
__global__ void __launch_bounds__(256) final_hmma_kernel(const float* __restrict__ V,
                                                         const float* __restrict__ cw,
                                                         float* __restrict__ out) {
    extern __shared__ unsigned char dsm[];
    uint32_t* K1hu  = (uint32_t*)dsm;        /* [128][66] u32 */
    uint32_t* K1lu  = K1hu + 8448;
    uint32_t* TmThu = K1hu + 16896;          /* [64][66] u32 : TmT[d][m] */
    uint32_t* TmTlu = K1hu + 21120;          /* total 25344 u32 = 101376 B */

    int t = threadIdx.x, lane = t & 31, w = t >> 5;
    int g = lane >> 2, tq = lane & 3;
    int bh = blockIdx.y, n0 = blockIdx.x * 128;
    const float* k1g = g_k1 + (size_t)bh * 524288 + (size_t)n0 * 128;
    const float* Tmg = g_Tm + bh * 8192;

    split_tile_128(k1g, K1hu, K1lu, t);
    for (int i = t; i < 4096; i += 256) {
        int d = i >> 6, mp = i & 63;
        float x = Tmg[(2 * mp) * 64 + d];
        float y = Tmg[(2 * mp + 1) * 64 + d];
        uint32_t h, l;
        split2(x, y, h, l);
        TmThu[d * 66 + mp] = h;
        TmTlu[d * 66 + mp] = l;
    }
    __syncthreads();

    float acc[8][4];
#pragma unroll
    for (int i = 0; i < 8; i++)
#pragma unroll
        for (int j = 0; j < 4; j++) acc[i][j] = 0.f;
    int rA = w * 16 + g;
#pragma unroll
    for (int ks = 0; ks < 8; ks++) {
        int ko = ks * 8 + tq;
        uint32_t ah0 = K1hu[rA * 66 + ko],       ah1 = K1hu[(rA + 8) * 66 + ko];
        uint32_t ah2 = K1hu[rA * 66 + ko + 4],   ah3 = K1hu[(rA + 8) * 66 + ko + 4];
        uint32_t al0 = K1lu[rA * 66 + ko],       al1 = K1lu[(rA + 8) * 66 + ko];
        uint32_t al2 = K1lu[rA * 66 + ko + 4],   al3 = K1lu[(rA + 8) * 66 + ko + 4];
#pragma unroll
        for (int tile = 0; tile < 8; tile++) {
            int n = tile * 8 + g;
            uint32_t bh0 = TmThu[n * 66 + ko], bh1 = TmThu[n * 66 + ko + 4];
            uint32_t bl0 = TmTlu[n * 66 + ko], bl1 = TmTlu[n * 66 + ko + 4];
            MMA_BF16(acc[tile], ah0, ah1, ah2, ah3, bh0, bh1);
            MMA_BF16(acc[tile], ah0, ah1, ah2, ah3, bl0, bl1);
            MMA_BF16(acc[tile], al0, al1, al2, al3, bh0, bh1);
        }
    }

    int h = bh & 15;
    float w0 = cw[h * 3], w1 = cw[h * 3 + 1], w2 = cw[h * 3 + 2];
    const float* Vh = V + (size_t)bh * 262144;
    float* oh = out + (size_t)bh * 262144;
#pragma unroll
    for (int tile = 0; tile < 8; tile++) {
        int d = tile * 8 + 2 * tq;
#pragma unroll
        for (int rr = 0; rr < 2; rr++) {
            int n = n0 + w * 16 + g + rr * 8;
            float a0 = acc[tile][rr * 2], a1 = acc[tile][rr * 2 + 1];
            float2 vc = *(const float2*)&Vh[(size_t)n * 64 + d];
            float2 vp = (n > 0)    ? *(const float2*)&Vh[(size_t)(n - 1) * 64 + d] : make_float2(0.f, 0.f);
            float2 vn = (n < 4095) ? *(const float2*)&Vh[(size_t)(n + 1) * 64 + d] : make_float2(0.f, 0.f);
            float2 o;
            o.x = a0 + w0 * vp.x + w1 * vc.x + w2 * vn.x;
            o.y = a1 + w0 * vp.y + w1 * vc.y + w2 * vn.y;
            *(float2*)&oh[(size_t)n * 64 + d] = o;
        }
    }
}

/* ------------------ launch ------------------ */
extern "C" void kernel_launch(void* const* d_in, const int* in_sizes, int n_in,
                              void* d_out, int out_size) {
    (void)in_sizes; (void)n_in; (void)out_size;
    const float* Q     = (const float*)d_in[0];
    const float* V     = (const float*)d_in[1];
    const float* Wland = (const float*)d_in[2];
    const float* gamma = (const float*)d_in[3];
    const float* beta  = (const float*)d_in[4];
    const float* convw = (const float*)d_in[5];
    float* out = (float*)d_out;

    cudaFuncSetAttribute(k1_hmma_kernel,
                         cudaFuncAttributeMaxDynamicSharedMemorySize, 52224);
    cudaFuncSetAttribute(newton_persistent,
                         cudaFuncAttributeMaxDynamicSharedMemorySize, 152064);
    cudaFuncSetAttribute(final_hmma_kernel,
                         cudaFuncAttributeMaxDynamicSharedMemorySize, 101376);
    cudaFuncSetAttribute(k2_prep_kernel,
                         cudaFuncAttributeMaxDynamicSharedMemorySize, 66048);
    cudaFuncSetAttribute(kv_hmma_kernel,
                         cudaFuncAttributeMaxDynamicSharedMemorySize, 101888);

    wtrans_kernel<<<512, 256>>>(Wland);
    landmark_kernel<<<dim3(4, BH), 256>>>(Q, gamma, beta);
    k2_prep_kernel<<<BH, 256, 66048>>>();
    k1_hmma_kernel<<<dim3(32, BH), 256, 51712>>>(Q);
    alpha_kernel<<<1, 256>>>();
    vminit_kernel<<<512, 256>>>();
    newton_persistent<<<NBLK, 256, 152064>>>();
    kv_hmma_kernel<<<dim3(8, BH), 256, 101888>>>(V);
    mm_tm<<<dim3(2, BH), 256>>>();
    final_hmma_kernel<<<dim3(32, BH), 256, 101376>>>(V, convw, out);
}